// round 10
// baseline (speedup 1.0000x reference)
#include <cuda_runtime.h>
#include <cuda_bf16.h>
#include <cstdint>

#define B_  8
#define T_  2048
#define NH  4
#define HD  32
#define CE  128
#define QKVS 384
#define NTOK (B_ * T_)

// softmax scale * log2(e)
#define SC2 (0.17677669529663687f * 1.4426950408889634f)

// ---------------------------------------------------------------------------
// Device-global scratch
// ---------------------------------------------------------------------------
__device__ float g_y[(size_t)NTOK * CE];       // fp32 [tok][128]
__device__ __nv_bfloat16 g_qh[(size_t)NTOK * CE], g_ql[(size_t)NTOK * CE];
__device__ __nv_bfloat16 g_kh[(size_t)NTOK * CE], g_kl[(size_t)NTOK * CE];
__device__ __nv_bfloat16 g_vh[(size_t)NTOK * CE], g_vl[(size_t)NTOK * CE];

// ---------------------------------------------------------------------------
// helpers
// ---------------------------------------------------------------------------
__device__ __forceinline__ uint32_t smem_u32(const void* p) {
    return (uint32_t)__cvta_generic_to_shared(p);
}
__device__ __forceinline__ void ldmx4(uint32_t& r0, uint32_t& r1, uint32_t& r2,
                                      uint32_t& r3, uint32_t addr) {
    asm volatile("ldmatrix.sync.aligned.m8n8.x4.shared.b16 {%0,%1,%2,%3}, [%4];"
                 : "=r"(r0), "=r"(r1), "=r"(r2), "=r"(r3) : "r"(addr));
}
__device__ __forceinline__ void ldmx4t(uint32_t& r0, uint32_t& r1, uint32_t& r2,
                                       uint32_t& r3, uint32_t addr) {
    asm volatile("ldmatrix.sync.aligned.m8n8.x4.trans.shared.b16 {%0,%1,%2,%3}, [%4];"
                 : "=r"(r0), "=r"(r1), "=r"(r2), "=r"(r3) : "r"(addr));
}
__device__ __forceinline__ void mma16816(float (&c)[4], const uint32_t (&a)[4],
                                         uint32_t b0, uint32_t b1) {
    asm volatile(
        "mma.sync.aligned.m16n8k16.row.col.f32.bf16.bf16.f32 "
        "{%0,%1,%2,%3}, {%4,%5,%6,%7}, {%8,%9}, {%0,%1,%2,%3};"
        : "+f"(c[0]), "+f"(c[1]), "+f"(c[2]), "+f"(c[3])
        : "r"(a[0]), "r"(a[1]), "r"(a[2]), "r"(a[3]), "r"(b0), "r"(b1));
}
__device__ __forceinline__ float ex2f(float x) {
    float r; asm("ex2.approx.f32 %0, %1;" : "=f"(r) : "f"(x)); return r;
}
__device__ __forceinline__ uint32_t packbf(float a, float b) {
    __nv_bfloat162 t = __floats2bfloat162_rn(a, b);
    return *reinterpret_cast<uint32_t*>(&t);
}
__device__ __forceinline__ void split2pack(float a, float b,
                                           __nv_bfloat16* ph, __nv_bfloat16* pl) {
    __nv_bfloat162 hi = __floats2bfloat162_rn(a, b);
    *reinterpret_cast<__nv_bfloat162*>(ph) = hi;
    float ra = a - __bfloat162float(__low2bfloat16(hi));
    float rb = b - __bfloat162float(__high2bfloat16(hi));
    *reinterpret_cast<__nv_bfloat162*>(pl) = __floats2bfloat162_rn(ra, rb);
}
__device__ __forceinline__ float bfres(float a) {
    return a - __bfloat162float(__float2bfloat16(a));
}
__device__ __forceinline__ void cp16(uint32_t dst, const void* src) {
    asm volatile("cp.async.cg.shared.global [%0], [%1], 16;" :: "r"(dst), "l"(src)
                 : "memory");
}

// ---------------------------------------------------------------------------
// GEMM via bf16 mma (3-term hi/lo), templated column-tile width BN.
// 256 threads, BM=128, BK=32.
// MODE 0 (BN=128): A = x, epilogue splits into g_q/g_k/g_v hi/lo (q scaled);
//                  each CTA column tile is exactly one of q|k|v.
// MODE 1 (BN=64):  A = g_y, C = fp32 out + bias (unchanged from R9).
// ---------------------------------------------------------------------------
template <int MODE, int BN>
__global__ __launch_bounds__(256, 2) void gemm_mma(
    const float* __restrict__ Ap, const float* __restrict__ W,
    const float* __restrict__ bias, float* __restrict__ Cp, int N)
{
    constexpr int NP = BN / 16;      // n-fragment pairs per warp row
    constexpr int WS = BN + 8;       // W smem row stride (bf16)
    const float* A = (MODE == 0) ? Ap : g_y;
    const int K = CE;

    __shared__ __nv_bfloat16 Ah[128 * 40], Al[128 * 40];   // [row][k] pad 40
    __shared__ __nv_bfloat16 Wh[32 * (128 + 8)], Wl[32 * (128 + 8)];

    const int tid = threadIdx.x;
    const int w   = tid >> 5;
    const int l   = tid & 31;
    const int bm0 = blockIdx.x * 128;
    const int bn0 = blockIdx.y * BN;

    float acc[2 * NP][4];
    #pragma unroll
    for (int i = 0; i < 2 * NP; i++)
        #pragma unroll
        for (int j = 0; j < 4; j++) acc[i][j] = 0.f;

    for (int k0 = 0; k0 < 128; k0 += 32) {
        if (k0) __syncthreads();
        // A chunk 128x32: 1024 float4
        #pragma unroll
        for (int it = 0; it < 4; it++) {
            int fid = tid + it * 256;
            int r = fid >> 3, c4 = (fid & 7) << 2;
            float4 v = *(const float4*)(A + (size_t)(bm0 + r) * K + k0 + c4);
            split2pack(v.x, v.y, &Ah[r * 40 + c4],     &Al[r * 40 + c4]);
            split2pack(v.z, v.w, &Ah[r * 40 + c4 + 2], &Al[r * 40 + c4 + 2]);
        }
        // W chunk 32xBN: 32*BN/4 float4
        #pragma unroll
        for (int it = 0; it < BN / 32; it++) {
            int fid = tid + it * 256;
            int r = fid / (BN / 4), cc = fid % (BN / 4);
            int c4 = cc << 2;
            float4 v = *(const float4*)(W + (size_t)(k0 + r) * N + bn0 + c4);
            split2pack(v.x, v.y, &Wh[r * WS + c4],     &Wl[r * WS + c4]);
            split2pack(v.z, v.w, &Wh[r * WS + c4 + 2], &Wl[r * WS + c4 + 2]);
        }
        __syncthreads();

        uint32_t ahf[2][4], alf[2][4];
        #pragma unroll
        for (int ks2 = 0; ks2 < 2; ks2++) {
            int off = (w * 16 + (l & 7) + ((l >> 3) & 1) * 8) * 40
                      + ks2 * 16 + ((l >> 4) & 1) * 8;
            ldmx4(ahf[ks2][0], ahf[ks2][1], ahf[ks2][2], ahf[ks2][3], smem_u32(&Ah[off]));
            ldmx4(alf[ks2][0], alf[ks2][1], alf[ks2][2], alf[ks2][3], smem_u32(&Al[off]));
        }
        #pragma unroll
        for (int ks2 = 0; ks2 < 2; ks2++) {
            #pragma unroll
            for (int np = 0; np < NP; np++) {
                int off = (ks2 * 16 + ((l >> 3) & 1) * 8 + (l & 7)) * WS
                          + np * 16 + ((l >> 4) & 1) * 8;
                uint32_t wh0, wh1, wh2, wh3, wl0, wl1, wl2, wl3;
                ldmx4t(wh0, wh1, wh2, wh3, smem_u32(&Wh[off]));
                ldmx4t(wl0, wl1, wl2, wl3, smem_u32(&Wl[off]));
                mma16816(acc[2 * np],     ahf[ks2], wh0, wh1);
                mma16816(acc[2 * np],     ahf[ks2], wl0, wl1);
                mma16816(acc[2 * np],     alf[ks2], wh0, wh1);
                mma16816(acc[2 * np + 1], ahf[ks2], wh2, wh3);
                mma16816(acc[2 * np + 1], ahf[ks2], wl2, wl3);
                mma16816(acc[2 * np + 1], alf[ks2], wh2, wh3);
            }
        }
    }

    const int g = l >> 2, j2 = (l & 3) * 2;
    if (MODE == 0) {
        // BN=128: each column tile is exactly one section (0=q 1=k 2=v)
        int sect = bn0 >> 7;
        __nv_bfloat16 *dh, *dl;
        float mul;
        if (sect == 0)      { dh = g_qh; dl = g_ql; mul = SC2; }
        else if (sect == 1) { dh = g_kh; dl = g_kl; mul = 1.f; }
        else                { dh = g_vh; dl = g_vl; mul = 1.f; }
        #pragma unroll
        for (int nt = 0; nt < 2 * NP; nt++) {
            int n = bn0 + nt * 8 + j2;
            int col = nt * 8 + j2;
            float b0 = bias[n], b1 = bias[n + 1];
            int r0 = bm0 + w * 16 + g;
            split2pack((acc[nt][0] + b0) * mul, (acc[nt][1] + b1) * mul,
                       dh + (size_t)r0 * CE + col, dl + (size_t)r0 * CE + col);
            split2pack((acc[nt][2] + b0) * mul, (acc[nt][3] + b1) * mul,
                       dh + (size_t)(r0 + 8) * CE + col, dl + (size_t)(r0 + 8) * CE + col);
        }
    } else {
        #pragma unroll
        for (int nt = 0; nt < 2 * NP; nt++) {
            int n = bn0 + nt * 8 + j2;
            float b0 = bias[n], b1 = bias[n + 1];
            float* p0 = Cp + (size_t)(bm0 + w * 16 + g) * N + n;
            float* p1 = Cp + (size_t)(bm0 + w * 16 + 8 + g) * N + n;
            *(float2*)p0 = make_float2(acc[nt][0] + b0, acc[nt][1] + b1);
            *(float2*)p1 = make_float2(acc[nt][2] + b0, acc[nt][3] + b1);
        }
    }
}

// ---------------------------------------------------------------------------
// Flash attention (R9 verbatim except occupancy 2 -> 3).
// 128 threads (4 warps x 32 query rows = 128-row Q tile), KV tile 64.
// Q fragments direct from global; K/V via cp.async double buffer.
// ---------------------------------------------------------------------------
__global__ __launch_bounds__(128, 3) void attn_mma()
{
    __shared__ __nv_bfloat16 sm[2][4][64 * 40];  // [stage][kh,kl,vh,vl]

    const int tid = threadIdx.x;
    const int w   = tid >> 5;
    const int l   = tid & 31;
    const int qt  = 15 - blockIdx.x;  // heavy tiles first
    const int hh  = blockIdx.y;
    const int b   = blockIdx.z;
    const int qr0 = qt * 128;
    const int bT  = b * T_;
    const int hoff = hh * HD;
    const int nkv = 2 * qt + 2;

    // Q fragments straight from global (a-frag layout)
    uint32_t qhf[2][2][4], qlf[2][2][4];
    {
        int r = l >> 2, c2 = (l & 3) * 2;
        #pragma unroll
        for (int s = 0; s < 2; s++)
            #pragma unroll
            for (int ks2 = 0; ks2 < 2; ks2++) {
                size_t p = (size_t)(bT + qr0 + w * 32 + s * 16 + r) * CE
                           + hoff + ks2 * 16 + c2;
                qhf[s][ks2][0] = *(const uint32_t*)(g_qh + p);
                qhf[s][ks2][1] = *(const uint32_t*)(g_qh + p + 8 * CE);
                qhf[s][ks2][2] = *(const uint32_t*)(g_qh + p + 8);
                qhf[s][ks2][3] = *(const uint32_t*)(g_qh + p + 8 * CE + 8);
                qlf[s][ks2][0] = *(const uint32_t*)(g_ql + p);
                qlf[s][ks2][1] = *(const uint32_t*)(g_ql + p + 8 * CE);
                qlf[s][ks2][2] = *(const uint32_t*)(g_ql + p + 8);
                qlf[s][ks2][3] = *(const uint32_t*)(g_ql + p + 8 * CE + 8);
            }
    }

    auto prefetch = [&](int st, int kt) {
        int kn0 = kt * 64;
        #pragma unroll
        for (int it = 0; it < 8; it++) {
            const int arr = it >> 1;
            int sub = tid + (it & 1) * 128;
            int row = sub >> 2, j = sub & 3;
            const __nv_bfloat16* gp =
                (arr == 0) ? g_kh : (arr == 1) ? g_kl : (arr == 2) ? g_vh : g_vl;
            const __nv_bfloat16* src = gp + (size_t)(bT + kn0 + row) * CE + hoff + j * 8;
            cp16(smem_u32(&sm[st][arr][row * 40 + j * 8]), src);
        }
        asm volatile("cp.async.commit_group;" ::: "memory");
    };

    auto softmax_update = [&](float (&s)[8][4], float* m2, float* li, float (&o)[4][4]) {
        float mx0 = -1e30f, mx1 = -1e30f;
        #pragma unroll
        for (int nt = 0; nt < 8; nt++) {
            mx0 = fmaxf(mx0, fmaxf(s[nt][0], s[nt][1]));
            mx1 = fmaxf(mx1, fmaxf(s[nt][2], s[nt][3]));
        }
        mx0 = fmaxf(mx0, __shfl_xor_sync(0xffffffffu, mx0, 1));
        mx0 = fmaxf(mx0, __shfl_xor_sync(0xffffffffu, mx0, 2));
        mx1 = fmaxf(mx1, __shfl_xor_sync(0xffffffffu, mx1, 1));
        mx1 = fmaxf(mx1, __shfl_xor_sync(0xffffffffu, mx1, 2));
        float mn0 = fmaxf(m2[0], mx0), mn1 = fmaxf(m2[1], mx1);
        float al0 = ex2f(m2[0] - mn0), al1 = ex2f(m2[1] - mn1);
        m2[0] = mn0; m2[1] = mn1;
        float rs0 = 0.f, rs1 = 0.f;
        #pragma unroll
        for (int nt = 0; nt < 8; nt++) {
            s[nt][0] = ex2f(s[nt][0] - mn0);
            s[nt][1] = ex2f(s[nt][1] - mn0);
            s[nt][2] = ex2f(s[nt][2] - mn1);
            s[nt][3] = ex2f(s[nt][3] - mn1);
            rs0 += s[nt][0] + s[nt][1];
            rs1 += s[nt][2] + s[nt][3];
        }
        rs0 += __shfl_xor_sync(0xffffffffu, rs0, 1);
        rs0 += __shfl_xor_sync(0xffffffffu, rs0, 2);
        rs1 += __shfl_xor_sync(0xffffffffu, rs1, 1);
        rs1 += __shfl_xor_sync(0xffffffffu, rs1, 2);
        li[0] = li[0] * al0 + rs0;
        li[1] = li[1] * al1 + rs1;
        #pragma unroll
        for (int nt = 0; nt < 4; nt++) {
            o[nt][0] *= al0; o[nt][1] *= al0;
            o[nt][2] *= al1; o[nt][3] *= al1;
        }
    };

    float m2[4] = {-1e30f, -1e30f, -1e30f, -1e30f};
    float li[4] = {0.f, 0.f, 0.f, 0.f};
    float o0[4][4], o1[4][4];
    #pragma unroll
    for (int i = 0; i < 4; i++)
        #pragma unroll
        for (int j = 0; j < 4; j++) { o0[i][j] = 0.f; o1[i][j] = 0.f; }

    prefetch(0, 0);

    for (int kt = 0; kt < nkv; kt++) {
        const int kn0 = kt * 64;
        const int st = kt & 1;
        if (kt + 1 < nkv) {
            prefetch(st ^ 1, kt + 1);
            asm volatile("cp.async.wait_group 1;" ::: "memory");
        } else {
            asm volatile("cp.async.wait_group 0;" ::: "memory");
        }
        __syncthreads();

        if (kn0 <= qr0 + w * 32 + 31) {  // warp has unmasked work
            const __nv_bfloat16* KhS = sm[st][0];
            const __nv_bfloat16* KlS = sm[st][1];
            const __nv_bfloat16* VhS = sm[st][2];
            const __nv_bfloat16* VlS = sm[st][3];

            float s0[8][4], s1[8][4];
            #pragma unroll
            for (int i = 0; i < 8; i++)
                #pragma unroll
                for (int j = 0; j < 4; j++) { s0[i][j] = 0.f; s1[i][j] = 0.f; }

            // ---- S = Q @ K^T (K frags shared by both strips) ----
            #pragma unroll
            for (int ks2 = 0; ks2 < 2; ks2++) {
                #pragma unroll
                for (int np = 0; np < 4; np++) {
                    int off = (np * 16 + ((l >> 4) & 1) * 8 + (l & 7)) * 40
                              + ks2 * 16 + ((l >> 3) & 1) * 8;
                    uint32_t kh0, kh1, kh2, kh3, kl0, kl1, kl2, kl3;
                    ldmx4(kh0, kh1, kh2, kh3, smem_u32(KhS + off));
                    ldmx4(kl0, kl1, kl2, kl3, smem_u32(KlS + off));
                    mma16816(s0[2 * np],     qhf[0][ks2], kh0, kh1);
                    mma16816(s0[2 * np],     qhf[0][ks2], kl0, kl1);
                    mma16816(s0[2 * np],     qlf[0][ks2], kh0, kh1);
                    mma16816(s0[2 * np + 1], qhf[0][ks2], kh2, kh3);
                    mma16816(s0[2 * np + 1], qhf[0][ks2], kl2, kl3);
                    mma16816(s0[2 * np + 1], qlf[0][ks2], kh2, kh3);
                    mma16816(s1[2 * np],     qhf[1][ks2], kh0, kh1);
                    mma16816(s1[2 * np],     qhf[1][ks2], kl0, kl1);
                    mma16816(s1[2 * np],     qlf[1][ks2], kh0, kh1);
                    mma16816(s1[2 * np + 1], qhf[1][ks2], kh2, kh3);
                    mma16816(s1[2 * np + 1], qhf[1][ks2], kl2, kl3);
                    mma16816(s1[2 * np + 1], qlf[1][ks2], kh2, kh3);
                }
            }

            // ---- causal mask ----
            if (kn0 + 63 > qr0 + w * 32) {
                int r0 = qr0 + w * 32 + (l >> 2);
                #pragma unroll
                for (int nt = 0; nt < 8; nt++) {
                    int c = kn0 + nt * 8 + (l & 3) * 2;
                    if (c > r0)          s0[nt][0] = -1e30f;
                    if (c + 1 > r0)      s0[nt][1] = -1e30f;
                    if (c > r0 + 8)      s0[nt][2] = -1e30f;
                    if (c + 1 > r0 + 8)  s0[nt][3] = -1e30f;
                    if (c > r0 + 16)     s1[nt][0] = -1e30f;
                    if (c + 1 > r0 + 16) s1[nt][1] = -1e30f;
                    if (c > r0 + 24)     s1[nt][2] = -1e30f;
                    if (c + 1 > r0 + 24) s1[nt][3] = -1e30f;
                }
            }

            softmax_update(s0, &m2[0], &li[0], o0);
            softmax_update(s1, &m2[2], &li[2], o1);

            // ---- O += P @ V (V frags shared by both strips; 3-term hi/lo) ----
            #pragma unroll
            for (int kk = 0; kk < 4; kk++) {
                uint32_t a0[4], a1[4], a0l[4], a1l[4];
                a0[0]  = packbf(s0[2 * kk][0],     s0[2 * kk][1]);
                a0[1]  = packbf(s0[2 * kk][2],     s0[2 * kk][3]);
                a0[2]  = packbf(s0[2 * kk + 1][0], s0[2 * kk + 1][1]);
                a0[3]  = packbf(s0[2 * kk + 1][2], s0[2 * kk + 1][3]);
                a0l[0] = packbf(bfres(s0[2 * kk][0]),     bfres(s0[2 * kk][1]));
                a0l[1] = packbf(bfres(s0[2 * kk][2]),     bfres(s0[2 * kk][3]));
                a0l[2] = packbf(bfres(s0[2 * kk + 1][0]), bfres(s0[2 * kk + 1][1]));
                a0l[3] = packbf(bfres(s0[2 * kk + 1][2]), bfres(s0[2 * kk + 1][3]));
                a1[0]  = packbf(s1[2 * kk][0],     s1[2 * kk][1]);
                a1[1]  = packbf(s1[2 * kk][2],     s1[2 * kk][3]);
                a1[2]  = packbf(s1[2 * kk + 1][0], s1[2 * kk + 1][1]);
                a1[3]  = packbf(s1[2 * kk + 1][2], s1[2 * kk + 1][3]);
                a1l[0] = packbf(bfres(s1[2 * kk][0]),     bfres(s1[2 * kk][1]));
                a1l[1] = packbf(bfres(s1[2 * kk][2]),     bfres(s1[2 * kk][3]));
                a1l[2] = packbf(bfres(s1[2 * kk + 1][0]), bfres(s1[2 * kk + 1][1]));
                a1l[3] = packbf(bfres(s1[2 * kk + 1][2]), bfres(s1[2 * kk + 1][3]));
                #pragma unroll
                for (int np = 0; np < 2; np++) {
                    int off = (kk * 16 + ((l >> 3) & 1) * 8 + (l & 7)) * 40
                              + np * 16 + ((l >> 4) & 1) * 8;
                    uint32_t vh0, vh1, vh2, vh3, vl0, vl1, vl2, vl3;
                    ldmx4t(vh0, vh1, vh2, vh3, smem_u32(VhS + off));
                    ldmx4t(vl0, vl1, vl2, vl3, smem_u32(VlS + off));
                    mma16816(o0[2 * np],     a0,  vh0, vh1);
                    mma16816(o0[2 * np],     a0,  vl0, vl1);
                    mma16816(o0[2 * np],     a0l, vh0, vh1);
                    mma16816(o0[2 * np + 1], a0,  vh2, vh3);
                    mma16816(o0[2 * np + 1], a0,  vl2, vl3);
                    mma16816(o0[2 * np + 1], a0l, vh2, vh3);
                    mma16816(o1[2 * np],     a1,  vh0, vh1);
                    mma16816(o1[2 * np],     a1,  vl0, vl1);
                    mma16816(o1[2 * np],     a1l, vh0, vh1);
                    mma16816(o1[2 * np + 1], a1,  vh2, vh3);
                    mma16816(o1[2 * np + 1], a1,  vl2, vl3);
                    mma16816(o1[2 * np + 1], a1l, vh2, vh3);
                }
            }
        }
        __syncthreads();
    }

    // ---- epilogue: normalize, write fp32 y ----
    #pragma unroll
    for (int s = 0; s < 2; s++) {
        float (&o)[4][4] = s ? o1 : o0;
        #pragma unroll
        for (int g = 0; g < 2; g++) {
            float inv = 1.f / li[s * 2 + g];
            int row = qr0 + w * 32 + s * 16 + g * 8 + (l >> 2);
            size_t yb = (size_t)(bT + row) * CE + hoff;
            #pragma unroll
            for (int nt = 0; nt < 4; nt++) {
                int d = nt * 8 + (l & 3) * 2;
                *(float2*)(g_y + yb + d) =
                    make_float2(o[nt][g * 2] * inv, o[nt][g * 2 + 1] * inv);
            }
        }
    }
}

// ---------------------------------------------------------------------------
extern "C" void kernel_launch(void* const* d_in, const int* in_sizes, int n_in,
                              void* d_out, int out_size)
{
    const float* x      = (const float*)d_in[0];
    const float* w_qkv  = (const float*)d_in[1];
    const float* b_qkv  = (const float*)d_in[2];
    const float* w_proj = (const float*)d_in[3];
    const float* b_proj = (const float*)d_in[4];
    float* out = (float*)d_out;

    // 1) qkv projection -> g_q/g_k/g_v hi/lo (q pre-scaled), split fused
    gemm_mma<0, 128><<<dim3(NTOK / 128, QKVS / 128), 256>>>(x, w_qkv, b_qkv, nullptr, QKVS);

    // 2) attention -> g_y (fp32)
    attn_mma<<<dim3(T_ / 128, NH, B_), 128>>>();

    // 3) out = g_y @ w_proj + b_proj
    gemm_mma<1, 64><<<dim3(NTOK / 128, CE / 64), 256>>>(nullptr, w_proj, b_proj, out, CE);
}

// round 14
// speedup vs baseline: 2.1092x; 2.1092x over previous
#include <cuda_runtime.h>
#include <cuda_bf16.h>
#include <cuda_fp16.h>
#include <cstdint>

#define B_  8
#define T_  2048
#define NH  4
#define HD  32
#define CE  128
#define QKVS 384
#define NTOK (B_ * T_)

// softmax scale * log2(e)
#define SC2 (0.17677669529663687f * 1.4426950408889634f)

// ---------------------------------------------------------------------------
// Device-global scratch.  q: fp16 hi/lo (pre-scaled); k: fp16 single;
// v: fp16 hi/lo; y: fp32.
// ---------------------------------------------------------------------------
__device__ float g_y[(size_t)NTOK * CE];
__device__ __half g_qh[(size_t)NTOK * CE], g_ql[(size_t)NTOK * CE];
__device__ __half g_kh[(size_t)NTOK * CE], g_kl[(size_t)NTOK * CE];  // kl written, unused
__device__ __half g_vh[(size_t)NTOK * CE], g_vl[(size_t)NTOK * CE];

// ---------------------------------------------------------------------------
// helpers
// ---------------------------------------------------------------------------
__device__ __forceinline__ uint32_t smem_u32(const void* p) {
    return (uint32_t)__cvta_generic_to_shared(p);
}
__device__ __forceinline__ void ldmx4(uint32_t& r0, uint32_t& r1, uint32_t& r2,
                                      uint32_t& r3, uint32_t addr) {
    asm volatile("ldmatrix.sync.aligned.m8n8.x4.shared.b16 {%0,%1,%2,%3}, [%4];"
                 : "=r"(r0), "=r"(r1), "=r"(r2), "=r"(r3) : "r"(addr));
}
__device__ __forceinline__ void ldmx4t(uint32_t& r0, uint32_t& r1, uint32_t& r2,
                                       uint32_t& r3, uint32_t addr) {
    asm volatile("ldmatrix.sync.aligned.m8n8.x4.trans.shared.b16 {%0,%1,%2,%3}, [%4];"
                 : "=r"(r0), "=r"(r1), "=r"(r2), "=r"(r3) : "r"(addr));
}
// bf16 mma (GEMM path, unchanged numerics)
__device__ __forceinline__ void mma16816(float (&c)[4], const uint32_t (&a)[4],
                                         uint32_t b0, uint32_t b1) {
    asm volatile(
        "mma.sync.aligned.m16n8k16.row.col.f32.bf16.bf16.f32 "
        "{%0,%1,%2,%3}, {%4,%5,%6,%7}, {%8,%9}, {%0,%1,%2,%3};"
        : "+f"(c[0]), "+f"(c[1]), "+f"(c[2]), "+f"(c[3])
        : "r"(a[0]), "r"(a[1]), "r"(a[2]), "r"(a[3]), "r"(b0), "r"(b1));
}
// fp16 mma (attention path)
__device__ __forceinline__ void mma16816h(float (&c)[4], const uint32_t (&a)[4],
                                          uint32_t b0, uint32_t b1) {
    asm volatile(
        "mma.sync.aligned.m16n8k16.row.col.f32.f16.f16.f32 "
        "{%0,%1,%2,%3}, {%4,%5,%6,%7}, {%8,%9}, {%0,%1,%2,%3};"
        : "+f"(c[0]), "+f"(c[1]), "+f"(c[2]), "+f"(c[3])
        : "r"(a[0]), "r"(a[1]), "r"(a[2]), "r"(a[3]), "r"(b0), "r"(b1));
}
__device__ __forceinline__ float ex2f(float x) {
    float r; asm("ex2.approx.f32 %0, %1;" : "=f"(r) : "f"(x)); return r;
}
__device__ __forceinline__ uint32_t packh(float a, float b) {
    __half2 t = __floats2half2_rn(a, b);
    return *reinterpret_cast<uint32_t*>(&t);
}
// bf16 hi/lo split (GEMM smem staging — unchanged from R9)
__device__ __forceinline__ void split2pack(float a, float b,
                                           __nv_bfloat16* ph, __nv_bfloat16* pl) {
    __nv_bfloat162 hi = __floats2bfloat162_rn(a, b);
    *reinterpret_cast<__nv_bfloat162*>(ph) = hi;
    float ra = a - __bfloat162float(__low2bfloat16(hi));
    float rb = b - __bfloat162float(__high2bfloat16(hi));
    *reinterpret_cast<__nv_bfloat162*>(pl) = __floats2bfloat162_rn(ra, rb);
}
// fp16 hi/lo split (q/k/v store)
__device__ __forceinline__ void splith(float a, float b, __half* ph, __half* pl) {
    __half2 hi = __floats2half2_rn(a, b);
    *reinterpret_cast<__half2*>(ph) = hi;
    float ra = a - __half2float(__low2half(hi));
    float rb = b - __half2float(__high2half(hi));
    *reinterpret_cast<__half2*>(pl) = __floats2half2_rn(ra, rb);
}
__device__ __forceinline__ void cp16(uint32_t dst, const void* src) {
    asm volatile("cp.async.cg.shared.global [%0], [%1], 16;" :: "r"(dst), "l"(src)
                 : "memory");
}

// ---------------------------------------------------------------------------
// GEMM via bf16 mma (R9 verbatim body; MODE 0 epilogue stores fp16 hi/lo).
// 256 threads, BM=128, BN=64, BK=32.
// MODE 0: A = param (x), epilogue -> g_q/g_k/g_v (q pre-scaled)
// MODE 1: A = g_y, C = fp32 out + bias
// ---------------------------------------------------------------------------
template <int MODE>
__global__ __launch_bounds__(256) void gemm_mma(
    const float* __restrict__ Ap, const float* __restrict__ W,
    const float* __restrict__ bias, float* __restrict__ Cp, int N)
{
    const float* A = (MODE == 0) ? Ap : g_y;
    const int K = CE;

    __shared__ __nv_bfloat16 Ah[128 * 40], Al[128 * 40];  // [row][k] pad 40
    __shared__ __nv_bfloat16 Wh[32 * 72],  Wl[32 * 72];   // [k][n]  pad 72

    const int tid = threadIdx.x;
    const int w   = tid >> 5;
    const int l   = tid & 31;
    const int bm0 = blockIdx.x * 128;
    const int bn0 = blockIdx.y * 64;

    float acc[8][4];
    #pragma unroll
    for (int i = 0; i < 8; i++)
        #pragma unroll
        for (int j = 0; j < 4; j++) acc[i][j] = 0.f;

    for (int k0 = 0; k0 < 128; k0 += 32) {
        if (k0) __syncthreads();
        // A chunk 128x32: 1024 float4
        #pragma unroll
        for (int it = 0; it < 4; it++) {
            int fid = tid + it * 256;
            int r = fid >> 3, c4 = (fid & 7) << 2;
            float4 v = *(const float4*)(A + (size_t)(bm0 + r) * K + k0 + c4);
            split2pack(v.x, v.y, &Ah[r * 40 + c4],     &Al[r * 40 + c4]);
            split2pack(v.z, v.w, &Ah[r * 40 + c4 + 2], &Al[r * 40 + c4 + 2]);
        }
        // W chunk 32x64: 512 float4
        #pragma unroll
        for (int it = 0; it < 2; it++) {
            int fid = tid + it * 256;
            int r = fid >> 4, c4 = (fid & 15) << 2;
            float4 v = *(const float4*)(W + (size_t)(k0 + r) * N + bn0 + c4);
            split2pack(v.x, v.y, &Wh[r * 72 + c4],     &Wl[r * 72 + c4]);
            split2pack(v.z, v.w, &Wh[r * 72 + c4 + 2], &Wl[r * 72 + c4 + 2]);
        }
        __syncthreads();

        uint32_t ahf[2][4], alf[2][4];
        #pragma unroll
        for (int ks2 = 0; ks2 < 2; ks2++) {
            int off = (w * 16 + (l & 7) + ((l >> 3) & 1) * 8) * 40
                      + ks2 * 16 + ((l >> 4) & 1) * 8;
            ldmx4(ahf[ks2][0], ahf[ks2][1], ahf[ks2][2], ahf[ks2][3], smem_u32(&Ah[off]));
            ldmx4(alf[ks2][0], alf[ks2][1], alf[ks2][2], alf[ks2][3], smem_u32(&Al[off]));
        }
        #pragma unroll
        for (int ks2 = 0; ks2 < 2; ks2++) {
            #pragma unroll
            for (int np = 0; np < 4; np++) {
                int off = (ks2 * 16 + ((l >> 3) & 1) * 8 + (l & 7)) * 72
                          + np * 16 + ((l >> 4) & 1) * 8;
                uint32_t wh0, wh1, wh2, wh3, wl0, wl1, wl2, wl3;
                ldmx4t(wh0, wh1, wh2, wh3, smem_u32(&Wh[off]));
                ldmx4t(wl0, wl1, wl2, wl3, smem_u32(&Wl[off]));
                mma16816(acc[2 * np],     ahf[ks2], wh0, wh1);
                mma16816(acc[2 * np],     ahf[ks2], wl0, wl1);
                mma16816(acc[2 * np],     alf[ks2], wh0, wh1);
                mma16816(acc[2 * np + 1], ahf[ks2], wh2, wh3);
                mma16816(acc[2 * np + 1], ahf[ks2], wl2, wl3);
                mma16816(acc[2 * np + 1], alf[ks2], wh2, wh3);
            }
        }
    }

    const int g = l >> 2, j2 = (l & 3) * 2;
    if (MODE == 0) {
        int sect = bn0 >> 7;  // 0=q 1=k 2=v
        __half *dh, *dl;
        float mul;
        if (sect == 0)      { dh = g_qh; dl = g_ql; mul = SC2; }
        else if (sect == 1) { dh = g_kh; dl = g_kl; mul = 1.f; }
        else                { dh = g_vh; dl = g_vl; mul = 1.f; }
        #pragma unroll
        for (int nt = 0; nt < 8; nt++) {
            int n = bn0 + nt * 8 + j2;
            int col = n & 127;
            float b0 = bias[n], b1 = bias[n + 1];
            int r0 = bm0 + w * 16 + g;
            splith((acc[nt][0] + b0) * mul, (acc[nt][1] + b1) * mul,
                   dh + (size_t)r0 * CE + col, dl + (size_t)r0 * CE + col);
            splith((acc[nt][2] + b0) * mul, (acc[nt][3] + b1) * mul,
                   dh + (size_t)(r0 + 8) * CE + col, dl + (size_t)(r0 + 8) * CE + col);
        }
    } else {
        #pragma unroll
        for (int nt = 0; nt < 8; nt++) {
            int n = bn0 + nt * 8 + j2;
            float b0 = bias[n], b1 = bias[n + 1];
            float* p0 = Cp + (size_t)(bm0 + w * 16 + g) * N + n;
            float* p1 = Cp + (size_t)(bm0 + w * 16 + 8 + g) * N + n;
            *(float2*)p0 = make_float2(acc[nt][0] + b0, acc[nt][1] + b1);
            *(float2*)p1 = make_float2(acc[nt][2] + b0, acc[nt][3] + b1);
        }
    }
}

// ---------------------------------------------------------------------------
// Flash attention, fp16 2-term. 128 threads (4 warps x 32 query rows),
// KV tile 64; cp.async double buffer (3 arrays: K, Vh, Vl).
// S = (Qh + Ql) @ K^T ;  O += fp16(P) @ (Vh + Vl).
// ---------------------------------------------------------------------------
__global__ __launch_bounds__(128, 2) void attn_mma()
{
    __shared__ __half sm[2][3][64 * 40];  // [stage][k, vh, vl]

    const int tid = threadIdx.x;
    const int w   = tid >> 5;
    const int l   = tid & 31;
    const int qt  = 15 - blockIdx.x;  // heavy tiles first
    const int hh  = blockIdx.y;
    const int b   = blockIdx.z;
    const int qr0 = qt * 128;
    const int bT  = b * T_;
    const int hoff = hh * HD;
    const int nkv = 2 * qt + 2;

    // Q fragments (fp16 hi/lo) straight from global (a-frag layout)
    uint32_t qhf[2][2][4], qlf[2][2][4];
    {
        int r = l >> 2, c2 = (l & 3) * 2;
        #pragma unroll
        for (int s = 0; s < 2; s++)
            #pragma unroll
            for (int ks2 = 0; ks2 < 2; ks2++) {
                size_t p = (size_t)(bT + qr0 + w * 32 + s * 16 + r) * CE
                           + hoff + ks2 * 16 + c2;
                qhf[s][ks2][0] = *(const uint32_t*)(g_qh + p);
                qhf[s][ks2][1] = *(const uint32_t*)(g_qh + p + 8 * CE);
                qhf[s][ks2][2] = *(const uint32_t*)(g_qh + p + 8);
                qhf[s][ks2][3] = *(const uint32_t*)(g_qh + p + 8 * CE + 8);
                qlf[s][ks2][0] = *(const uint32_t*)(g_ql + p);
                qlf[s][ks2][1] = *(const uint32_t*)(g_ql + p + 8 * CE);
                qlf[s][ks2][2] = *(const uint32_t*)(g_ql + p + 8);
                qlf[s][ks2][3] = *(const uint32_t*)(g_ql + p + 8 * CE + 8);
            }
    }

    auto prefetch = [&](int st, int kt) {
        int kn0 = kt * 64;
        #pragma unroll
        for (int it = 0; it < 6; it++) {
            const int arr = it >> 1;             // 0=k 1=vh 2=vl
            int sub = tid + (it & 1) * 128;
            int row = sub >> 2, j = sub & 3;
            const __half* gp = (arr == 0) ? g_kh : (arr == 1) ? g_vh : g_vl;
            const __half* src = gp + (size_t)(bT + kn0 + row) * CE + hoff + j * 8;
            cp16(smem_u32(&sm[st][arr][row * 40 + j * 8]), src);
        }
        asm volatile("cp.async.commit_group;" ::: "memory");
    };

    auto softmax_update = [&](float (&s)[8][4], float* m2, float* li, float (&o)[4][4]) {
        float mx0 = -1e30f, mx1 = -1e30f;
        #pragma unroll
        for (int nt = 0; nt < 8; nt++) {
            mx0 = fmaxf(mx0, fmaxf(s[nt][0], s[nt][1]));
            mx1 = fmaxf(mx1, fmaxf(s[nt][2], s[nt][3]));
        }
        mx0 = fmaxf(mx0, __shfl_xor_sync(0xffffffffu, mx0, 1));
        mx0 = fmaxf(mx0, __shfl_xor_sync(0xffffffffu, mx0, 2));
        mx1 = fmaxf(mx1, __shfl_xor_sync(0xffffffffu, mx1, 1));
        mx1 = fmaxf(mx1, __shfl_xor_sync(0xffffffffu, mx1, 2));
        float mn0 = fmaxf(m2[0], mx0), mn1 = fmaxf(m2[1], mx1);
        float al0 = ex2f(m2[0] - mn0), al1 = ex2f(m2[1] - mn1);
        m2[0] = mn0; m2[1] = mn1;
        float rs0 = 0.f, rs1 = 0.f;
        #pragma unroll
        for (int nt = 0; nt < 8; nt++) {
            s[nt][0] = ex2f(s[nt][0] - mn0);
            s[nt][1] = ex2f(s[nt][1] - mn0);
            s[nt][2] = ex2f(s[nt][2] - mn1);
            s[nt][3] = ex2f(s[nt][3] - mn1);
            rs0 += s[nt][0] + s[nt][1];
            rs1 += s[nt][2] + s[nt][3];
        }
        rs0 += __shfl_xor_sync(0xffffffffu, rs0, 1);
        rs0 += __shfl_xor_sync(0xffffffffu, rs0, 2);
        rs1 += __shfl_xor_sync(0xffffffffu, rs1, 1);
        rs1 += __shfl_xor_sync(0xffffffffu, rs1, 2);
        li[0] = li[0] * al0 + rs0;
        li[1] = li[1] * al1 + rs1;
        #pragma unroll
        for (int nt = 0; nt < 4; nt++) {
            o[nt][0] *= al0; o[nt][1] *= al0;
            o[nt][2] *= al1; o[nt][3] *= al1;
        }
    };

    float m2[4] = {-1e30f, -1e30f, -1e30f, -1e30f};
    float li[4] = {0.f, 0.f, 0.f, 0.f};
    float o0[4][4], o1[4][4];
    #pragma unroll
    for (int i = 0; i < 4; i++)
        #pragma unroll
        for (int j = 0; j < 4; j++) { o0[i][j] = 0.f; o1[i][j] = 0.f; }

    prefetch(0, 0);

    for (int kt = 0; kt < nkv; kt++) {
        const int kn0 = kt * 64;
        const int st = kt & 1;
        if (kt + 1 < nkv) {
            prefetch(st ^ 1, kt + 1);
            asm volatile("cp.async.wait_group 1;" ::: "memory");
        } else {
            asm volatile("cp.async.wait_group 0;" ::: "memory");
        }
        __syncthreads();

        if (kn0 <= qr0 + w * 32 + 31) {  // warp has unmasked work
            const __half* KS  = sm[st][0];
            const __half* VhS = sm[st][1];
            const __half* VlS = sm[st][2];

            float s0[8][4], s1[8][4];
            #pragma unroll
            for (int i = 0; i < 8; i++)
                #pragma unroll
                for (int j = 0; j < 4; j++) { s0[i][j] = 0.f; s1[i][j] = 0.f; }

            // ---- S = (Qh + Ql) @ K^T (K frags shared by both strips) ----
            #pragma unroll
            for (int ks2 = 0; ks2 < 2; ks2++) {
                #pragma unroll
                for (int np = 0; np < 4; np++) {
                    int off = (np * 16 + ((l >> 4) & 1) * 8 + (l & 7)) * 40
                              + ks2 * 16 + ((l >> 3) & 1) * 8;
                    uint32_t k0, k1, k2, k3;
                    ldmx4(k0, k1, k2, k3, smem_u32(KS + off));
                    mma16816h(s0[2 * np],     qhf[0][ks2], k0, k1);
                    mma16816h(s0[2 * np],     qlf[0][ks2], k0, k1);
                    mma16816h(s0[2 * np + 1], qhf[0][ks2], k2, k3);
                    mma16816h(s0[2 * np + 1], qlf[0][ks2], k2, k3);
                    mma16816h(s1[2 * np],     qhf[1][ks2], k0, k1);
                    mma16816h(s1[2 * np],     qlf[1][ks2], k0, k1);
                    mma16816h(s1[2 * np + 1], qhf[1][ks2], k2, k3);
                    mma16816h(s1[2 * np + 1], qlf[1][ks2], k2, k3);
                }
            }

            // ---- causal mask ----
            if (kn0 + 63 > qr0 + w * 32) {
                int r0 = qr0 + w * 32 + (l >> 2);
                #pragma unroll
                for (int nt = 0; nt < 8; nt++) {
                    int c = kn0 + nt * 8 + (l & 3) * 2;
                    if (c > r0)          s0[nt][0] = -1e30f;
                    if (c + 1 > r0)      s0[nt][1] = -1e30f;
                    if (c > r0 + 8)      s0[nt][2] = -1e30f;
                    if (c + 1 > r0 + 8)  s0[nt][3] = -1e30f;
                    if (c > r0 + 16)     s1[nt][0] = -1e30f;
                    if (c + 1 > r0 + 16) s1[nt][1] = -1e30f;
                    if (c > r0 + 24)     s1[nt][2] = -1e30f;
                    if (c + 1 > r0 + 24) s1[nt][3] = -1e30f;
                }
            }

            softmax_update(s0, &m2[0], &li[0], o0);
            softmax_update(s1, &m2[2], &li[2], o1);

            // ---- O += fp16(P) @ (Vh + Vl) (V frags shared by strips) ----
            #pragma unroll
            for (int kk = 0; kk < 4; kk++) {
                uint32_t a0[4], a1[4];
                a0[0] = packh(s0[2 * kk][0],     s0[2 * kk][1]);
                a0[1] = packh(s0[2 * kk][2],     s0[2 * kk][3]);
                a0[2] = packh(s0[2 * kk + 1][0], s0[2 * kk + 1][1]);
                a0[3] = packh(s0[2 * kk + 1][2], s0[2 * kk + 1][3]);
                a1[0] = packh(s1[2 * kk][0],     s1[2 * kk][1]);
                a1[1] = packh(s1[2 * kk][2],     s1[2 * kk][3]);
                a1[2] = packh(s1[2 * kk + 1][0], s1[2 * kk + 1][1]);
                a1[3] = packh(s1[2 * kk + 1][2], s1[2 * kk + 1][3]);
                #pragma unroll
                for (int np = 0; np < 2; np++) {
                    int off = (kk * 16 + ((l >> 3) & 1) * 8 + (l & 7)) * 40
                              + np * 16 + ((l >> 4) & 1) * 8;
                    uint32_t vh0, vh1, vh2, vh3, vl0, vl1, vl2, vl3;
                    ldmx4t(vh0, vh1, vh2, vh3, smem_u32(VhS + off));
                    ldmx4t(vl0, vl1, vl2, vl3, smem_u32(VlS + off));
                    mma16816h(o0[2 * np],     a0, vh0, vh1);
                    mma16816h(o0[2 * np],     a0, vl0, vl1);
                    mma16816h(o0[2 * np + 1], a0, vh2, vh3);
                    mma16816h(o0[2 * np + 1], a0, vl2, vl3);
                    mma16816h(o1[2 * np],     a1, vh0, vh1);
                    mma16816h(o1[2 * np],     a1, vl0, vl1);
                    mma16816h(o1[2 * np + 1], a1, vh2, vh3);
                    mma16816h(o1[2 * np + 1], a1, vl2, vl3);
                }
            }
        }
        __syncthreads();
    }

    // ---- epilogue: normalize, write fp32 y ----
    #pragma unroll
    for (int s = 0; s < 2; s++) {
        float (&o)[4][4] = s ? o1 : o0;
        #pragma unroll
        for (int g = 0; g < 2; g++) {
            float inv = 1.f / li[s * 2 + g];
            int row = qr0 + w * 32 + s * 16 + g * 8 + (l >> 2);
            size_t yb = (size_t)(bT + row) * CE + hoff;
            #pragma unroll
            for (int nt = 0; nt < 4; nt++) {
                int d = nt * 8 + (l & 3) * 2;
                *(float2*)(g_y + yb + d) =
                    make_float2(o[nt][g * 2] * inv, o[nt][g * 2 + 1] * inv);
            }
        }
    }
}

// ---------------------------------------------------------------------------
extern "C" void kernel_launch(void* const* d_in, const int* in_sizes, int n_in,
                              void* d_out, int out_size)
{
    const float* x      = (const float*)d_in[0];
    const float* w_qkv  = (const float*)d_in[1];
    const float* b_qkv  = (const float*)d_in[2];
    const float* w_proj = (const float*)d_in[3];
    const float* b_proj = (const float*)d_in[4];
    float* out = (float*)d_out;

    // 1) qkv projection -> g_q/g_k/g_v fp16 (q pre-scaled), split fused
    gemm_mma<0><<<dim3(NTOK / 128, QKVS / 64), 256>>>(x, w_qkv, b_qkv, nullptr, QKVS);

    // 2) attention (fp16 2-term) -> g_y (fp32)
    attn_mma<<<dim3(T_ / 128, NH, B_), 128>>>();

    // 3) out = g_y @ w_proj + b_proj
    gemm_mma<1><<<dim3(NTOK / 128, CE / 64), 256>>>(nullptr, w_proj, b_proj, out, CE);
}

// round 15
// speedup vs baseline: 2.9907x; 1.4180x over previous
#include <cuda_runtime.h>
#include <cuda_fp16.h>
#include <cstdint>

#define B_  8
#define T_  2048
#define NH  4
#define HD  32
#define CE  128
#define QKVS 384
#define NTOK (B_ * T_)

// softmax scale * log2(e)
#define SC2 (0.17677669529663687f * 1.4426950408889634f)

// ---------------------------------------------------------------------------
// Device-global scratch (all single fp16; q pre-scaled)
// ---------------------------------------------------------------------------
__device__ float g_y[(size_t)NTOK * CE];
__device__ __half g_q[(size_t)NTOK * CE];
__device__ __half g_k[(size_t)NTOK * CE];
__device__ __half g_v[(size_t)NTOK * CE];

// ---------------------------------------------------------------------------
// helpers
// ---------------------------------------------------------------------------
__device__ __forceinline__ uint32_t smem_u32(const void* p) {
    return (uint32_t)__cvta_generic_to_shared(p);
}
__device__ __forceinline__ void ldmx4(uint32_t& r0, uint32_t& r1, uint32_t& r2,
                                      uint32_t& r3, uint32_t addr) {
    asm volatile("ldmatrix.sync.aligned.m8n8.x4.shared.b16 {%0,%1,%2,%3}, [%4];"
                 : "=r"(r0), "=r"(r1), "=r"(r2), "=r"(r3) : "r"(addr));
}
__device__ __forceinline__ void ldmx4t(uint32_t& r0, uint32_t& r1, uint32_t& r2,
                                       uint32_t& r3, uint32_t addr) {
    asm volatile("ldmatrix.sync.aligned.m8n8.x4.trans.shared.b16 {%0,%1,%2,%3}, [%4];"
                 : "=r"(r0), "=r"(r1), "=r"(r2), "=r"(r3) : "r"(addr));
}
__device__ __forceinline__ void mma16816h(float (&c)[4], const uint32_t (&a)[4],
                                          uint32_t b0, uint32_t b1) {
    asm volatile(
        "mma.sync.aligned.m16n8k16.row.col.f32.f16.f16.f32 "
        "{%0,%1,%2,%3}, {%4,%5,%6,%7}, {%8,%9}, {%0,%1,%2,%3};"
        : "+f"(c[0]), "+f"(c[1]), "+f"(c[2]), "+f"(c[3])
        : "r"(a[0]), "r"(a[1]), "r"(a[2]), "r"(a[3]), "r"(b0), "r"(b1));
}
__device__ __forceinline__ float ex2f(float x) {
    float r; asm("ex2.approx.f32 %0, %1;" : "=f"(r) : "f"(x)); return r;
}
__device__ __forceinline__ uint32_t packh(float a, float b) {
    __half2 t = __floats2half2_rn(a, b);
    return *reinterpret_cast<uint32_t*>(&t);
}
__device__ __forceinline__ void cp16(uint32_t dst, const void* src) {
    asm volatile("cp.async.cg.shared.global [%0], [%1], 16;" :: "r"(dst), "l"(src)
                 : "memory");
}

// ---------------------------------------------------------------------------
// GEMM via single-term fp16 mma. 256 threads, BM=128, BN=64, BK=32.
// MODE 0: A = param (x), epilogue -> g_q/g_k/g_v fp16 (q pre-scaled)
// MODE 1: A = g_y, C = fp32 out + bias
// ---------------------------------------------------------------------------
template <int MODE>
__global__ __launch_bounds__(256) void gemm_mma(
    const float* __restrict__ Ap, const float* __restrict__ W,
    const float* __restrict__ bias, float* __restrict__ Cp, int N)
{
    const float* A = (MODE == 0) ? Ap : g_y;
    const int K = CE;

    __shared__ __half As[128 * 40];   // [row][k] pad 40
    __shared__ __half Ws[32 * 72];    // [k][n]  pad 72

    const int tid = threadIdx.x;
    const int w   = tid >> 5;
    const int l   = tid & 31;
    const int bm0 = blockIdx.x * 128;
    const int bn0 = blockIdx.y * 64;

    float acc[8][4];
    #pragma unroll
    for (int i = 0; i < 8; i++)
        #pragma unroll
        for (int j = 0; j < 4; j++) acc[i][j] = 0.f;

    for (int k0 = 0; k0 < 128; k0 += 32) {
        if (k0) __syncthreads();
        // A chunk 128x32: 1024 float4
        #pragma unroll
        for (int it = 0; it < 4; it++) {
            int fid = tid + it * 256;
            int r = fid >> 3, c4 = (fid & 7) << 2;
            float4 v = *(const float4*)(A + (size_t)(bm0 + r) * K + k0 + c4);
            *(__half2*)(As + r * 40 + c4)     = __floats2half2_rn(v.x, v.y);
            *(__half2*)(As + r * 40 + c4 + 2) = __floats2half2_rn(v.z, v.w);
        }
        // W chunk 32x64: 512 float4
        #pragma unroll
        for (int it = 0; it < 2; it++) {
            int fid = tid + it * 256;
            int r = fid >> 4, c4 = (fid & 15) << 2;
            float4 v = *(const float4*)(W + (size_t)(k0 + r) * N + bn0 + c4);
            *(__half2*)(Ws + r * 72 + c4)     = __floats2half2_rn(v.x, v.y);
            *(__half2*)(Ws + r * 72 + c4 + 2) = __floats2half2_rn(v.z, v.w);
        }
        __syncthreads();

        uint32_t af[2][4];
        #pragma unroll
        for (int ks2 = 0; ks2 < 2; ks2++) {
            int off = (w * 16 + (l & 7) + ((l >> 3) & 1) * 8) * 40
                      + ks2 * 16 + ((l >> 4) & 1) * 8;
            ldmx4(af[ks2][0], af[ks2][1], af[ks2][2], af[ks2][3], smem_u32(&As[off]));
        }
        #pragma unroll
        for (int ks2 = 0; ks2 < 2; ks2++) {
            #pragma unroll
            for (int np = 0; np < 4; np++) {
                int off = (ks2 * 16 + ((l >> 3) & 1) * 8 + (l & 7)) * 72
                          + np * 16 + ((l >> 4) & 1) * 8;
                uint32_t w0, w1, w2, w3;
                ldmx4t(w0, w1, w2, w3, smem_u32(&Ws[off]));
                mma16816h(acc[2 * np],     af[ks2], w0, w1);
                mma16816h(acc[2 * np + 1], af[ks2], w2, w3);
            }
        }
    }

    const int g = l >> 2, j2 = (l & 3) * 2;
    if (MODE == 0) {
        int sect = bn0 >> 7;  // 0=q 1=k 2=v
        __half* dst;
        float mul;
        if (sect == 0)      { dst = g_q; mul = SC2; }
        else if (sect == 1) { dst = g_k; mul = 1.f; }
        else                { dst = g_v; mul = 1.f; }
        #pragma unroll
        for (int nt = 0; nt < 8; nt++) {
            int n = bn0 + nt * 8 + j2;
            int col = n & 127;
            float b0 = bias[n], b1 = bias[n + 1];
            int r0 = bm0 + w * 16 + g;
            *(__half2*)(dst + (size_t)r0 * CE + col) =
                __floats2half2_rn((acc[nt][0] + b0) * mul, (acc[nt][1] + b1) * mul);
            *(__half2*)(dst + (size_t)(r0 + 8) * CE + col) =
                __floats2half2_rn((acc[nt][2] + b0) * mul, (acc[nt][3] + b1) * mul);
        }
    } else {
        #pragma unroll
        for (int nt = 0; nt < 8; nt++) {
            int n = bn0 + nt * 8 + j2;
            float b0 = bias[n], b1 = bias[n + 1];
            float* p0 = Cp + (size_t)(bm0 + w * 16 + g) * N + n;
            float* p1 = Cp + (size_t)(bm0 + w * 16 + 8 + g) * N + n;
            *(float2*)p0 = make_float2(acc[nt][0] + b0, acc[nt][1] + b1);
            *(float2*)p1 = make_float2(acc[nt][2] + b0, acc[nt][3] + b1);
        }
    }
}

// ---------------------------------------------------------------------------
// Flash attention, single fp16. 128 threads (4 warps x 32 query rows),
// KV tile 64; cp.async double buffer (2 arrays: K, V).
// ---------------------------------------------------------------------------
__global__ __launch_bounds__(128, 2) void attn_mma()
{
    __shared__ __half sm[2][2][64 * 40];  // [stage][k, v]

    const int tid = threadIdx.x;
    const int w   = tid >> 5;
    const int l   = tid & 31;
    const int qt  = 15 - blockIdx.x;  // heavy tiles first
    const int hh  = blockIdx.y;
    const int b   = blockIdx.z;
    const int qr0 = qt * 128;
    const int bT  = b * T_;
    const int hoff = hh * HD;
    const int nkv = 2 * qt + 2;

    // Q fragments (single fp16) straight from global (a-frag layout)
    uint32_t qf[2][2][4];
    {
        int r = l >> 2, c2 = (l & 3) * 2;
        #pragma unroll
        for (int s = 0; s < 2; s++)
            #pragma unroll
            for (int ks2 = 0; ks2 < 2; ks2++) {
                size_t p = (size_t)(bT + qr0 + w * 32 + s * 16 + r) * CE
                           + hoff + ks2 * 16 + c2;
                qf[s][ks2][0] = *(const uint32_t*)(g_q + p);
                qf[s][ks2][1] = *(const uint32_t*)(g_q + p + 8 * CE);
                qf[s][ks2][2] = *(const uint32_t*)(g_q + p + 8);
                qf[s][ks2][3] = *(const uint32_t*)(g_q + p + 8 * CE + 8);
            }
    }

    auto prefetch = [&](int st, int kt) {
        int kn0 = kt * 64;
        #pragma unroll
        for (int it = 0; it < 4; it++) {
            const int arr = it >> 1;             // 0=k 1=v
            int sub = tid + (it & 1) * 128;
            int row = sub >> 2, j = sub & 3;
            const __half* gp = (arr == 0) ? g_k : g_v;
            const __half* src = gp + (size_t)(bT + kn0 + row) * CE + hoff + j * 8;
            cp16(smem_u32(&sm[st][arr][row * 40 + j * 8]), src);
        }
        asm volatile("cp.async.commit_group;" ::: "memory");
    };

    auto softmax_update = [&](float (&s)[8][4], float* m2, float* li, float (&o)[4][4]) {
        float mx0 = -1e30f, mx1 = -1e30f;
        #pragma unroll
        for (int nt = 0; nt < 8; nt++) {
            mx0 = fmaxf(mx0, fmaxf(s[nt][0], s[nt][1]));
            mx1 = fmaxf(mx1, fmaxf(s[nt][2], s[nt][3]));
        }
        mx0 = fmaxf(mx0, __shfl_xor_sync(0xffffffffu, mx0, 1));
        mx0 = fmaxf(mx0, __shfl_xor_sync(0xffffffffu, mx0, 2));
        mx1 = fmaxf(mx1, __shfl_xor_sync(0xffffffffu, mx1, 1));
        mx1 = fmaxf(mx1, __shfl_xor_sync(0xffffffffu, mx1, 2));
        float mn0 = fmaxf(m2[0], mx0), mn1 = fmaxf(m2[1], mx1);
        float al0 = ex2f(m2[0] - mn0), al1 = ex2f(m2[1] - mn1);
        m2[0] = mn0; m2[1] = mn1;
        float rs0 = 0.f, rs1 = 0.f;
        #pragma unroll
        for (int nt = 0; nt < 8; nt++) {
            s[nt][0] = ex2f(s[nt][0] - mn0);
            s[nt][1] = ex2f(s[nt][1] - mn0);
            s[nt][2] = ex2f(s[nt][2] - mn1);
            s[nt][3] = ex2f(s[nt][3] - mn1);
            rs0 += s[nt][0] + s[nt][1];
            rs1 += s[nt][2] + s[nt][3];
        }
        rs0 += __shfl_xor_sync(0xffffffffu, rs0, 1);
        rs0 += __shfl_xor_sync(0xffffffffu, rs0, 2);
        rs1 += __shfl_xor_sync(0xffffffffu, rs1, 1);
        rs1 += __shfl_xor_sync(0xffffffffu, rs1, 2);
        li[0] = li[0] * al0 + rs0;
        li[1] = li[1] * al1 + rs1;
        #pragma unroll
        for (int nt = 0; nt < 4; nt++) {
            o[nt][0] *= al0; o[nt][1] *= al0;
            o[nt][2] *= al1; o[nt][3] *= al1;
        }
    };

    float m2[4] = {-1e30f, -1e30f, -1e30f, -1e30f};
    float li[4] = {0.f, 0.f, 0.f, 0.f};
    float o0[4][4], o1[4][4];
    #pragma unroll
    for (int i = 0; i < 4; i++)
        #pragma unroll
        for (int j = 0; j < 4; j++) { o0[i][j] = 0.f; o1[i][j] = 0.f; }

    prefetch(0, 0);

    for (int kt = 0; kt < nkv; kt++) {
        const int kn0 = kt * 64;
        const int st = kt & 1;
        if (kt + 1 < nkv) {
            prefetch(st ^ 1, kt + 1);
            asm volatile("cp.async.wait_group 1;" ::: "memory");
        } else {
            asm volatile("cp.async.wait_group 0;" ::: "memory");
        }
        __syncthreads();

        if (kn0 <= qr0 + w * 32 + 31) {  // warp has unmasked work
            const __half* KS = sm[st][0];
            const __half* VS = sm[st][1];

            float s0[8][4], s1[8][4];
            #pragma unroll
            for (int i = 0; i < 8; i++)
                #pragma unroll
                for (int j = 0; j < 4; j++) { s0[i][j] = 0.f; s1[i][j] = 0.f; }

            // ---- S = Q @ K^T (K frags shared by both strips) ----
            #pragma unroll
            for (int ks2 = 0; ks2 < 2; ks2++) {
                #pragma unroll
                for (int np = 0; np < 4; np++) {
                    int off = (np * 16 + ((l >> 4) & 1) * 8 + (l & 7)) * 40
                              + ks2 * 16 + ((l >> 3) & 1) * 8;
                    uint32_t k0, k1, k2, k3;
                    ldmx4(k0, k1, k2, k3, smem_u32(KS + off));
                    mma16816h(s0[2 * np],     qf[0][ks2], k0, k1);
                    mma16816h(s0[2 * np + 1], qf[0][ks2], k2, k3);
                    mma16816h(s1[2 * np],     qf[1][ks2], k0, k1);
                    mma16816h(s1[2 * np + 1], qf[1][ks2], k2, k3);
                }
            }

            // ---- causal mask ----
            if (kn0 + 63 > qr0 + w * 32) {
                int r0 = qr0 + w * 32 + (l >> 2);
                #pragma unroll
                for (int nt = 0; nt < 8; nt++) {
                    int c = kn0 + nt * 8 + (l & 3) * 2;
                    if (c > r0)          s0[nt][0] = -1e30f;
                    if (c + 1 > r0)      s0[nt][1] = -1e30f;
                    if (c > r0 + 8)      s0[nt][2] = -1e30f;
                    if (c + 1 > r0 + 8)  s0[nt][3] = -1e30f;
                    if (c > r0 + 16)     s1[nt][0] = -1e30f;
                    if (c + 1 > r0 + 16) s1[nt][1] = -1e30f;
                    if (c > r0 + 24)     s1[nt][2] = -1e30f;
                    if (c + 1 > r0 + 24) s1[nt][3] = -1e30f;
                }
            }

            softmax_update(s0, &m2[0], &li[0], o0);
            softmax_update(s1, &m2[2], &li[2], o1);

            // ---- O += fp16(P) @ V (V frags shared by both strips) ----
            #pragma unroll
            for (int kk = 0; kk < 4; kk++) {
                uint32_t a0[4], a1[4];
                a0[0] = packh(s0[2 * kk][0],     s0[2 * kk][1]);
                a0[1] = packh(s0[2 * kk][2],     s0[2 * kk][3]);
                a0[2] = packh(s0[2 * kk + 1][0], s0[2 * kk + 1][1]);
                a0[3] = packh(s0[2 * kk + 1][2], s0[2 * kk + 1][3]);
                a1[0] = packh(s1[2 * kk][0],     s1[2 * kk][1]);
                a1[1] = packh(s1[2 * kk][2],     s1[2 * kk][3]);
                a1[2] = packh(s1[2 * kk + 1][0], s1[2 * kk + 1][1]);
                a1[3] = packh(s1[2 * kk + 1][2], s1[2 * kk + 1][3]);
                #pragma unroll
                for (int np = 0; np < 2; np++) {
                    int off = (kk * 16 + ((l >> 3) & 1) * 8 + (l & 7)) * 40
                              + np * 16 + ((l >> 4) & 1) * 8;
                    uint32_t v0, v1, v2, v3;
                    ldmx4t(v0, v1, v2, v3, smem_u32(VS + off));
                    mma16816h(o0[2 * np],     a0, v0, v1);
                    mma16816h(o0[2 * np + 1], a0, v2, v3);
                    mma16816h(o1[2 * np],     a1, v0, v1);
                    mma16816h(o1[2 * np + 1], a1, v2, v3);
                }
            }
        }
        __syncthreads();
    }

    // ---- epilogue: normalize, write fp32 y ----
    #pragma unroll
    for (int s = 0; s < 2; s++) {
        float (&o)[4][4] = s ? o1 : o0;
        #pragma unroll
        for (int g = 0; g < 2; g++) {
            float inv = 1.f / li[s * 2 + g];
            int row = qr0 + w * 32 + s * 16 + g * 8 + (l >> 2);
            size_t yb = (size_t)(bT + row) * CE + hoff;
            #pragma unroll
            for (int nt = 0; nt < 4; nt++) {
                int d = nt * 8 + (l & 3) * 2;
                *(float2*)(g_y + yb + d) =
                    make_float2(o[nt][g * 2] * inv, o[nt][g * 2 + 1] * inv);
            }
        }
    }
}

// ---------------------------------------------------------------------------
extern "C" void kernel_launch(void* const* d_in, const int* in_sizes, int n_in,
                              void* d_out, int out_size)
{
    const float* x      = (const float*)d_in[0];
    const float* w_qkv  = (const float*)d_in[1];
    const float* b_qkv  = (const float*)d_in[2];
    const float* w_proj = (const float*)d_in[3];
    const float* b_proj = (const float*)d_in[4];
    float* out = (float*)d_out;

    // 1) qkv projection -> g_q/g_k/g_v fp16 (q pre-scaled)
    gemm_mma<0><<<dim3(NTOK / 128, QKVS / 64), 256>>>(x, w_qkv, b_qkv, nullptr, QKVS);

    // 2) attention (single fp16) -> g_y (fp32)
    attn_mma<<<dim3(T_ / 128, NH, B_), 128>>>();

    // 3) out = g_y @ w_proj + b_proj
    gemm_mma<1><<<dim3(NTOK / 128, CE / 64), 256>>>(nullptr, w_proj, b_proj, out, CE);
}

// round 16
// speedup vs baseline: 3.1750x; 1.0616x over previous
#include <cuda_runtime.h>
#include <cuda_fp16.h>
#include <cstdint>

#define B_  8
#define T_  2048
#define NH  4
#define HD  32
#define CE  128
#define QKVS 384
#define NTOK (B_ * T_)

// softmax scale * log2(e)
#define SC2 (0.17677669529663687f * 1.4426950408889634f)

// ---------------------------------------------------------------------------
// Device-global scratch (all single fp16; q pre-scaled)
// ---------------------------------------------------------------------------
__device__ float g_y[(size_t)NTOK * CE];
__device__ __half g_q[(size_t)NTOK * CE];
__device__ __half g_k[(size_t)NTOK * CE];
__device__ __half g_v[(size_t)NTOK * CE];

// ---------------------------------------------------------------------------
// helpers
// ---------------------------------------------------------------------------
__device__ __forceinline__ uint32_t smem_u32(const void* p) {
    return (uint32_t)__cvta_generic_to_shared(p);
}
__device__ __forceinline__ void ldmx4(uint32_t& r0, uint32_t& r1, uint32_t& r2,
                                      uint32_t& r3, uint32_t addr) {
    asm volatile("ldmatrix.sync.aligned.m8n8.x4.shared.b16 {%0,%1,%2,%3}, [%4];"
                 : "=r"(r0), "=r"(r1), "=r"(r2), "=r"(r3) : "r"(addr));
}
__device__ __forceinline__ void ldmx4t(uint32_t& r0, uint32_t& r1, uint32_t& r2,
                                       uint32_t& r3, uint32_t addr) {
    asm volatile("ldmatrix.sync.aligned.m8n8.x4.trans.shared.b16 {%0,%1,%2,%3}, [%4];"
                 : "=r"(r0), "=r"(r1), "=r"(r2), "=r"(r3) : "r"(addr));
}
__device__ __forceinline__ void mma16816h(float (&c)[4], const uint32_t (&a)[4],
                                          uint32_t b0, uint32_t b1) {
    asm volatile(
        "mma.sync.aligned.m16n8k16.row.col.f32.f16.f16.f32 "
        "{%0,%1,%2,%3}, {%4,%5,%6,%7}, {%8,%9}, {%0,%1,%2,%3};"
        : "+f"(c[0]), "+f"(c[1]), "+f"(c[2]), "+f"(c[3])
        : "r"(a[0]), "r"(a[1]), "r"(a[2]), "r"(a[3]), "r"(b0), "r"(b1));
}
__device__ __forceinline__ float ex2f(float x) {
    float r; asm("ex2.approx.f32 %0, %1;" : "=f"(r) : "f"(x)); return r;
}
__device__ __forceinline__ uint32_t packh(float a, float b) {
    __half2 t = __floats2half2_rn(a, b);
    return *reinterpret_cast<uint32_t*>(&t);
}
__device__ __forceinline__ void cp16(uint32_t dst, const void* src) {
    asm volatile("cp.async.cg.shared.global [%0], [%1], 16;" :: "r"(dst), "l"(src)
                 : "memory");
}

// ---------------------------------------------------------------------------
// GEMM via single-term fp16 mma, templated BN. 256 threads, BM=128, BK=32.
// MODE 0 (BN=128): A = x, grid.y selects q|k|v; epilogue -> fp16 (q scaled)
// MODE 1 (BN=128): A = g_y, C = fp32 out + bias
// ---------------------------------------------------------------------------
template <int MODE, int BN>
__global__ __launch_bounds__(256) void gemm_mma(
    const float* __restrict__ Ap, const float* __restrict__ W,
    const float* __restrict__ bias, float* __restrict__ Cp, int N)
{
    constexpr int NP = BN / 16;      // n-fragment pairs per warp
    constexpr int WS = BN + 8;       // W smem row stride
    const float* A = (MODE == 0) ? Ap : g_y;
    const int K = CE;

    __shared__ __half As[128 * 40];      // [row][k] pad 40
    __shared__ __half Wsm[32 * (128 + 8)];

    const int tid = threadIdx.x;
    const int w   = tid >> 5;
    const int l   = tid & 31;
    const int bm0 = blockIdx.x * 128;
    const int bn0 = blockIdx.y * BN;

    float acc[2 * NP][4];
    #pragma unroll
    for (int i = 0; i < 2 * NP; i++)
        #pragma unroll
        for (int j = 0; j < 4; j++) acc[i][j] = 0.f;

    for (int k0 = 0; k0 < 128; k0 += 32) {
        if (k0) __syncthreads();
        // A chunk 128x32: 1024 float4
        #pragma unroll
        for (int it = 0; it < 4; it++) {
            int fid = tid + it * 256;
            int r = fid >> 3, c4 = (fid & 7) << 2;
            float4 v = *(const float4*)(A + (size_t)(bm0 + r) * K + k0 + c4);
            *(__half2*)(As + r * 40 + c4)     = __floats2half2_rn(v.x, v.y);
            *(__half2*)(As + r * 40 + c4 + 2) = __floats2half2_rn(v.z, v.w);
        }
        // W chunk 32xBN
        #pragma unroll
        for (int it = 0; it < BN / 32; it++) {
            int fid = tid + it * 256;
            int r = fid / (BN / 4), cc = fid % (BN / 4);
            int c4 = cc << 2;
            float4 v = *(const float4*)(W + (size_t)(k0 + r) * N + bn0 + c4);
            *(__half2*)(Wsm + r * WS + c4)     = __floats2half2_rn(v.x, v.y);
            *(__half2*)(Wsm + r * WS + c4 + 2) = __floats2half2_rn(v.z, v.w);
        }
        __syncthreads();

        uint32_t af[2][4];
        #pragma unroll
        for (int ks2 = 0; ks2 < 2; ks2++) {
            int off = (w * 16 + (l & 7) + ((l >> 3) & 1) * 8) * 40
                      + ks2 * 16 + ((l >> 4) & 1) * 8;
            ldmx4(af[ks2][0], af[ks2][1], af[ks2][2], af[ks2][3], smem_u32(&As[off]));
        }
        #pragma unroll
        for (int ks2 = 0; ks2 < 2; ks2++) {
            #pragma unroll
            for (int np = 0; np < NP; np++) {
                int off = (ks2 * 16 + ((l >> 3) & 1) * 8 + (l & 7)) * WS
                          + np * 16 + ((l >> 4) & 1) * 8;
                uint32_t w0, w1, w2, w3;
                ldmx4t(w0, w1, w2, w3, smem_u32(&Wsm[off]));
                mma16816h(acc[2 * np],     af[ks2], w0, w1);
                mma16816h(acc[2 * np + 1], af[ks2], w2, w3);
            }
        }
    }

    const int g = l >> 2, j2 = (l & 3) * 2;
    if (MODE == 0) {
        // BN=128: each column tile is exactly one section (0=q 1=k 2=v)
        int sect = blockIdx.y;
        __half* dst;
        float mul;
        if (sect == 0)      { dst = g_q; mul = SC2; }
        else if (sect == 1) { dst = g_k; mul = 1.f; }
        else                { dst = g_v; mul = 1.f; }
        #pragma unroll
        for (int nt = 0; nt < 2 * NP; nt++) {
            int n = bn0 + nt * 8 + j2;
            int col = nt * 8 + j2;
            float b0 = bias[n], b1 = bias[n + 1];
            int r0 = bm0 + w * 16 + g;
            *(__half2*)(dst + (size_t)r0 * CE + col) =
                __floats2half2_rn((acc[nt][0] + b0) * mul, (acc[nt][1] + b1) * mul);
            *(__half2*)(dst + (size_t)(r0 + 8) * CE + col) =
                __floats2half2_rn((acc[nt][2] + b0) * mul, (acc[nt][3] + b1) * mul);
        }
    } else {
        #pragma unroll
        for (int nt = 0; nt < 2 * NP; nt++) {
            int n = bn0 + nt * 8 + j2;
            float b0 = bias[n], b1 = bias[n + 1];
            float* p0 = Cp + (size_t)(bm0 + w * 16 + g) * N + n;
            float* p1 = Cp + (size_t)(bm0 + w * 16 + 8 + g) * N + n;
            *(float2*)p0 = make_float2(acc[nt][0] + b0, acc[nt][1] + b1);
            *(float2*)p1 = make_float2(acc[nt][2] + b0, acc[nt][3] + b1);
        }
    }
}

// ---------------------------------------------------------------------------
// Flash attention, single fp16, occupancy 3. 128 threads (4 warps x 32 rows),
// KV tile 64; cp.async double buffer (2 arrays: K, V).
// ---------------------------------------------------------------------------
__global__ __launch_bounds__(128, 3) void attn_mma()
{
    __shared__ __half sm[2][2][64 * 40];  // [stage][k, v]

    const int tid = threadIdx.x;
    const int w   = tid >> 5;
    const int l   = tid & 31;
    const int qt  = 15 - blockIdx.x;  // heavy tiles first
    const int hh  = blockIdx.y;
    const int b   = blockIdx.z;
    const int qr0 = qt * 128;
    const int bT  = b * T_;
    const int hoff = hh * HD;
    const int nkv = 2 * qt + 2;

    // Q fragments (single fp16) straight from global (a-frag layout)
    uint32_t qf[2][2][4];
    {
        int r = l >> 2, c2 = (l & 3) * 2;
        #pragma unroll
        for (int s = 0; s < 2; s++)
            #pragma unroll
            for (int ks2 = 0; ks2 < 2; ks2++) {
                size_t p = (size_t)(bT + qr0 + w * 32 + s * 16 + r) * CE
                           + hoff + ks2 * 16 + c2;
                qf[s][ks2][0] = *(const uint32_t*)(g_q + p);
                qf[s][ks2][1] = *(const uint32_t*)(g_q + p + 8 * CE);
                qf[s][ks2][2] = *(const uint32_t*)(g_q + p + 8);
                qf[s][ks2][3] = *(const uint32_t*)(g_q + p + 8 * CE + 8);
            }
    }

    auto prefetch = [&](int st, int kt) {
        int kn0 = kt * 64;
        #pragma unroll
        for (int it = 0; it < 4; it++) {
            const int arr = it >> 1;             // 0=k 1=v
            int sub = tid + (it & 1) * 128;
            int row = sub >> 2, j = sub & 3;
            const __half* gp = (arr == 0) ? g_k : g_v;
            const __half* src = gp + (size_t)(bT + kn0 + row) * CE + hoff + j * 8;
            cp16(smem_u32(&sm[st][arr][row * 40 + j * 8]), src);
        }
        asm volatile("cp.async.commit_group;" ::: "memory");
    };

    auto softmax_update = [&](float (&s)[8][4], float* m2, float* li, float (&o)[4][4]) {
        float mx0 = -1e30f, mx1 = -1e30f;
        #pragma unroll
        for (int nt = 0; nt < 8; nt++) {
            mx0 = fmaxf(mx0, fmaxf(s[nt][0], s[nt][1]));
            mx1 = fmaxf(mx1, fmaxf(s[nt][2], s[nt][3]));
        }
        mx0 = fmaxf(mx0, __shfl_xor_sync(0xffffffffu, mx0, 1));
        mx0 = fmaxf(mx0, __shfl_xor_sync(0xffffffffu, mx0, 2));
        mx1 = fmaxf(mx1, __shfl_xor_sync(0xffffffffu, mx1, 1));
        mx1 = fmaxf(mx1, __shfl_xor_sync(0xffffffffu, mx1, 2));
        float mn0 = fmaxf(m2[0], mx0), mn1 = fmaxf(m2[1], mx1);
        float al0 = ex2f(m2[0] - mn0), al1 = ex2f(m2[1] - mn1);
        m2[0] = mn0; m2[1] = mn1;
        float rs0 = 0.f, rs1 = 0.f;
        #pragma unroll
        for (int nt = 0; nt < 8; nt++) {
            s[nt][0] = ex2f(s[nt][0] - mn0);
            s[nt][1] = ex2f(s[nt][1] - mn0);
            s[nt][2] = ex2f(s[nt][2] - mn1);
            s[nt][3] = ex2f(s[nt][3] - mn1);
            rs0 += s[nt][0] + s[nt][1];
            rs1 += s[nt][2] + s[nt][3];
        }
        rs0 += __shfl_xor_sync(0xffffffffu, rs0, 1);
        rs0 += __shfl_xor_sync(0xffffffffu, rs0, 2);
        rs1 += __shfl_xor_sync(0xffffffffu, rs1, 1);
        rs1 += __shfl_xor_sync(0xffffffffu, rs1, 2);
        li[0] = li[0] * al0 + rs0;
        li[1] = li[1] * al1 + rs1;
        #pragma unroll
        for (int nt = 0; nt < 4; nt++) {
            o[nt][0] *= al0; o[nt][1] *= al0;
            o[nt][2] *= al1; o[nt][3] *= al1;
        }
    };

    float m2[4] = {-1e30f, -1e30f, -1e30f, -1e30f};
    float li[4] = {0.f, 0.f, 0.f, 0.f};
    float o0[4][4], o1[4][4];
    #pragma unroll
    for (int i = 0; i < 4; i++)
        #pragma unroll
        for (int j = 0; j < 4; j++) { o0[i][j] = 0.f; o1[i][j] = 0.f; }

    prefetch(0, 0);

    for (int kt = 0; kt < nkv; kt++) {
        const int kn0 = kt * 64;
        const int st = kt & 1;
        if (kt + 1 < nkv) {
            prefetch(st ^ 1, kt + 1);
            asm volatile("cp.async.wait_group 1;" ::: "memory");
        } else {
            asm volatile("cp.async.wait_group 0;" ::: "memory");
        }
        __syncthreads();

        if (kn0 <= qr0 + w * 32 + 31) {  // warp has unmasked work
            const __half* KS = sm[st][0];
            const __half* VS = sm[st][1];

            float s0[8][4], s1[8][4];
            #pragma unroll
            for (int i = 0; i < 8; i++)
                #pragma unroll
                for (int j = 0; j < 4; j++) { s0[i][j] = 0.f; s1[i][j] = 0.f; }

            // ---- S = Q @ K^T (K frags shared by both strips) ----
            #pragma unroll
            for (int ks2 = 0; ks2 < 2; ks2++) {
                #pragma unroll
                for (int np = 0; np < 4; np++) {
                    int off = (np * 16 + ((l >> 4) & 1) * 8 + (l & 7)) * 40
                              + ks2 * 16 + ((l >> 3) & 1) * 8;
                    uint32_t k0, k1, k2, k3;
                    ldmx4(k0, k1, k2, k3, smem_u32(KS + off));
                    mma16816h(s0[2 * np],     qf[0][ks2], k0, k1);
                    mma16816h(s0[2 * np + 1], qf[0][ks2], k2, k3);
                    mma16816h(s1[2 * np],     qf[1][ks2], k0, k1);
                    mma16816h(s1[2 * np + 1], qf[1][ks2], k2, k3);
                }
            }

            // ---- causal mask ----
            if (kn0 + 63 > qr0 + w * 32) {
                int r0 = qr0 + w * 32 + (l >> 2);
                #pragma unroll
                for (int nt = 0; nt < 8; nt++) {
                    int c = kn0 + nt * 8 + (l & 3) * 2;
                    if (c > r0)          s0[nt][0] = -1e30f;
                    if (c + 1 > r0)      s0[nt][1] = -1e30f;
                    if (c > r0 + 8)      s0[nt][2] = -1e30f;
                    if (c + 1 > r0 + 8)  s0[nt][3] = -1e30f;
                    if (c > r0 + 16)     s1[nt][0] = -1e30f;
                    if (c + 1 > r0 + 16) s1[nt][1] = -1e30f;
                    if (c > r0 + 24)     s1[nt][2] = -1e30f;
                    if (c + 1 > r0 + 24) s1[nt][3] = -1e30f;
                }
            }

            softmax_update(s0, &m2[0], &li[0], o0);
            softmax_update(s1, &m2[2], &li[2], o1);

            // ---- O += fp16(P) @ V (V frags shared by both strips) ----
            #pragma unroll
            for (int kk = 0; kk < 4; kk++) {
                uint32_t a0[4], a1[4];
                a0[0] = packh(s0[2 * kk][0],     s0[2 * kk][1]);
                a0[1] = packh(s0[2 * kk][2],     s0[2 * kk][3]);
                a0[2] = packh(s0[2 * kk + 1][0], s0[2 * kk + 1][1]);
                a0[3] = packh(s0[2 * kk + 1][2], s0[2 * kk + 1][3]);
                a1[0] = packh(s1[2 * kk][0],     s1[2 * kk][1]);
                a1[1] = packh(s1[2 * kk][2],     s1[2 * kk][3]);
                a1[2] = packh(s1[2 * kk + 1][0], s1[2 * kk + 1][1]);
                a1[3] = packh(s1[2 * kk + 1][2], s1[2 * kk + 1][3]);
                #pragma unroll
                for (int np = 0; np < 2; np++) {
                    int off = (kk * 16 + ((l >> 3) & 1) * 8 + (l & 7)) * 40
                              + np * 16 + ((l >> 4) & 1) * 8;
                    uint32_t v0, v1, v2, v3;
                    ldmx4t(v0, v1, v2, v3, smem_u32(VS + off));
                    mma16816h(o0[2 * np],     a0, v0, v1);
                    mma16816h(o0[2 * np + 1], a0, v2, v3);
                    mma16816h(o1[2 * np],     a1, v0, v1);
                    mma16816h(o1[2 * np + 1], a1, v2, v3);
                }
            }
        }
        __syncthreads();
    }

    // ---- epilogue: normalize, write fp32 y ----
    #pragma unroll
    for (int s = 0; s < 2; s++) {
        float (&o)[4][4] = s ? o1 : o0;
        #pragma unroll
        for (int g = 0; g < 2; g++) {
            float inv = 1.f / li[s * 2 + g];
            int row = qr0 + w * 32 + s * 16 + g * 8 + (l >> 2);
            size_t yb = (size_t)(bT + row) * CE + hoff;
            #pragma unroll
            for (int nt = 0; nt < 4; nt++) {
                int d = nt * 8 + (l & 3) * 2;
                *(float2*)(g_y + yb + d) =
                    make_float2(o[nt][g * 2] * inv, o[nt][g * 2 + 1] * inv);
            }
        }
    }
}

// ---------------------------------------------------------------------------
extern "C" void kernel_launch(void* const* d_in, const int* in_sizes, int n_in,
                              void* d_out, int out_size)
{
    const float* x      = (const float*)d_in[0];
    const float* w_qkv  = (const float*)d_in[1];
    const float* b_qkv  = (const float*)d_in[2];
    const float* w_proj = (const float*)d_in[3];
    const float* b_proj = (const float*)d_in[4];
    float* out = (float*)d_out;

    // 1) qkv projection -> g_q/g_k/g_v fp16 (q pre-scaled)
    gemm_mma<0, 128><<<dim3(NTOK / 128, 3), 256>>>(x, w_qkv, b_qkv, nullptr, QKVS);

    // 2) attention (single fp16) -> g_y (fp32)
    attn_mma<<<dim3(T_ / 128, NH, B_), 128>>>();

    // 3) out = g_y @ w_proj + b_proj
    gemm_mma<1, 128><<<dim3(NTOK / 128, 1), 256>>>(nullptr, w_proj, b_proj, out, CE);
}

// round 17
// speedup vs baseline: 3.2294x; 1.0171x over previous
#include <cuda_runtime.h>
#include <cuda_fp16.h>
#include <cstdint>

#define B_  8
#define T_  2048
#define NH  4
#define HD  32
#define CE  128
#define QKVS 384
#define NTOK (B_ * T_)

// softmax scale * log2(e)
#define SC2 (0.17677669529663687f * 1.4426950408889634f)

// ---------------------------------------------------------------------------
// Device-global scratch (all single fp16; q pre-scaled)
// ---------------------------------------------------------------------------
__device__ float g_y[(size_t)NTOK * CE];
__device__ __half g_q[(size_t)NTOK * CE];
__device__ __half g_k[(size_t)NTOK * CE];
__device__ __half g_v[(size_t)NTOK * CE];

// ---------------------------------------------------------------------------
// helpers
// ---------------------------------------------------------------------------
__device__ __forceinline__ uint32_t smem_u32(const void* p) {
    return (uint32_t)__cvta_generic_to_shared(p);
}
__device__ __forceinline__ void ldmx4(uint32_t& r0, uint32_t& r1, uint32_t& r2,
                                      uint32_t& r3, uint32_t addr) {
    asm volatile("ldmatrix.sync.aligned.m8n8.x4.shared.b16 {%0,%1,%2,%3}, [%4];"
                 : "=r"(r0), "=r"(r1), "=r"(r2), "=r"(r3) : "r"(addr));
}
__device__ __forceinline__ void ldmx4t(uint32_t& r0, uint32_t& r1, uint32_t& r2,
                                       uint32_t& r3, uint32_t addr) {
    asm volatile("ldmatrix.sync.aligned.m8n8.x4.trans.shared.b16 {%0,%1,%2,%3}, [%4];"
                 : "=r"(r0), "=r"(r1), "=r"(r2), "=r"(r3) : "r"(addr));
}
__device__ __forceinline__ void mma16816h(float (&c)[4], const uint32_t (&a)[4],
                                          uint32_t b0, uint32_t b1) {
    asm volatile(
        "mma.sync.aligned.m16n8k16.row.col.f32.f16.f16.f32 "
        "{%0,%1,%2,%3}, {%4,%5,%6,%7}, {%8,%9}, {%0,%1,%2,%3};"
        : "+f"(c[0]), "+f"(c[1]), "+f"(c[2]), "+f"(c[3])
        : "r"(a[0]), "r"(a[1]), "r"(a[2]), "r"(a[3]), "r"(b0), "r"(b1));
}
__device__ __forceinline__ float ex2f(float x) {
    float r; asm("ex2.approx.f32 %0, %1;" : "=f"(r) : "f"(x)); return r;
}
__device__ __forceinline__ uint32_t packh(float a, float b) {
    __half2 t = __floats2half2_rn(a, b);
    return *reinterpret_cast<uint32_t*>(&t);
}
__device__ __forceinline__ void cp16(uint32_t dst, const void* src) {
    asm volatile("cp.async.cg.shared.global [%0], [%1], 16;" :: "r"(dst), "l"(src)
                 : "memory");
}

// ---------------------------------------------------------------------------
// GEMM via single-term fp16 mma; A staged ONCE, sections looped in-kernel.
// 128 threads (4 warps x 16 rows), BM=64, BN=128 per section, BK=32.
// MODE 0: A = x (NSECT=3 -> q|k|v, q pre-scaled fp16 out)
// MODE 1: A = g_y (NSECT=1 -> fp32 out + bias)
// ---------------------------------------------------------------------------
template <int MODE>
__global__ __launch_bounds__(128) void gemm_mma(
    const float* __restrict__ Ap, const float* __restrict__ W,
    const float* __restrict__ bias, float* __restrict__ Cp, int N)
{
    constexpr int NSECT = (MODE == 0) ? 3 : 1;
    const float* A = (MODE == 0) ? Ap : g_y;

    __shared__ __half As[64 * 136];   // full A tile [row][k], stride 136
    __shared__ __half Ws[32 * 136];   // W chunk [k][n], stride 136

    const int tid = threadIdx.x;
    const int w   = tid >> 5;
    const int l   = tid & 31;
    const int bm0 = blockIdx.x * 64;

    // ---- stage full A [64,128] fp32 -> fp16, once ----
    #pragma unroll
    for (int it = 0; it < 16; it++) {
        int fid = tid + it * 128;            // < 2048 float4
        int r = fid >> 5, c4 = (fid & 31) << 2;
        float4 v = *(const float4*)(A + (size_t)(bm0 + r) * CE + c4);
        *(__half2*)(As + r * 136 + c4)     = __floats2half2_rn(v.x, v.y);
        *(__half2*)(As + r * 136 + c4 + 2) = __floats2half2_rn(v.z, v.w);
    }

    for (int sect = 0; sect < NSECT; sect++) {
        const int bn0 = sect * 128;
        float acc[16][4];
        #pragma unroll
        for (int i = 0; i < 16; i++)
            #pragma unroll
            for (int j = 0; j < 4; j++) acc[i][j] = 0.f;

        for (int k0 = 0; k0 < 128; k0 += 32) {
            if (sect || k0) __syncthreads();   // protect Ws rewrite
            // W chunk 32x128: 1024 float4
            #pragma unroll
            for (int it = 0; it < 8; it++) {
                int fid = tid + it * 128;
                int r = fid >> 5, c4 = (fid & 31) << 2;
                float4 v = *(const float4*)(W + (size_t)(k0 + r) * N + bn0 + c4);
                *(__half2*)(Ws + r * 136 + c4)     = __floats2half2_rn(v.x, v.y);
                *(__half2*)(Ws + r * 136 + c4 + 2) = __floats2half2_rn(v.z, v.w);
            }
            __syncthreads();

            uint32_t af[2][4];
            #pragma unroll
            for (int ks2 = 0; ks2 < 2; ks2++) {
                int off = (w * 16 + (l & 7) + ((l >> 3) & 1) * 8) * 136
                          + k0 + ks2 * 16 + ((l >> 4) & 1) * 8;
                ldmx4(af[ks2][0], af[ks2][1], af[ks2][2], af[ks2][3],
                      smem_u32(&As[off]));
            }
            #pragma unroll
            for (int ks2 = 0; ks2 < 2; ks2++) {
                #pragma unroll
                for (int np = 0; np < 8; np++) {
                    int off = (ks2 * 16 + ((l >> 3) & 1) * 8 + (l & 7)) * 136
                              + np * 16 + ((l >> 4) & 1) * 8;
                    uint32_t w0, w1, w2, w3;
                    ldmx4t(w0, w1, w2, w3, smem_u32(&Ws[off]));
                    mma16816h(acc[2 * np],     af[ks2], w0, w1);
                    mma16816h(acc[2 * np + 1], af[ks2], w2, w3);
                }
            }
        }

        const int g = l >> 2, j2 = (l & 3) * 2;
        if (MODE == 0) {
            __half* dst;
            float mul;
            if (sect == 0)      { dst = g_q; mul = SC2; }
            else if (sect == 1) { dst = g_k; mul = 1.f; }
            else                { dst = g_v; mul = 1.f; }
            #pragma unroll
            for (int nt = 0; nt < 16; nt++) {
                int n = bn0 + nt * 8 + j2;
                int col = nt * 8 + j2;
                float b0 = bias[n], b1 = bias[n + 1];
                int r0 = bm0 + w * 16 + g;
                *(__half2*)(dst + (size_t)r0 * CE + col) =
                    __floats2half2_rn((acc[nt][0] + b0) * mul, (acc[nt][1] + b1) * mul);
                *(__half2*)(dst + (size_t)(r0 + 8) * CE + col) =
                    __floats2half2_rn((acc[nt][2] + b0) * mul, (acc[nt][3] + b1) * mul);
            }
        } else {
            #pragma unroll
            for (int nt = 0; nt < 16; nt++) {
                int n = nt * 8 + j2;
                float b0 = bias[n], b1 = bias[n + 1];
                float* p0 = Cp + (size_t)(bm0 + w * 16 + g) * N + n;
                float* p1 = Cp + (size_t)(bm0 + w * 16 + 8 + g) * N + n;
                *(float2*)p0 = make_float2(acc[nt][0] + b0, acc[nt][1] + b1);
                *(float2*)p1 = make_float2(acc[nt][2] + b0, acc[nt][3] + b1);
            }
        }
    }
}

// ---------------------------------------------------------------------------
// Flash attention, single fp16, occ 3, 4-stage cp.async ring with ONE
// __syncthreads per KV-iter. 128 threads (4 warps x 32 rows), KV tile 64.
// ---------------------------------------------------------------------------
__global__ __launch_bounds__(128, 3) void attn_mma()
{
    __shared__ __half sm[4][2][64 * 40];  // [stage][k, v]

    const int tid = threadIdx.x;
    const int w   = tid >> 5;
    const int l   = tid & 31;
    const int qt  = 15 - blockIdx.x;  // heavy tiles first
    const int hh  = blockIdx.y;
    const int b   = blockIdx.z;
    const int qr0 = qt * 128;
    const int bT  = b * T_;
    const int hoff = hh * HD;
    const int nkv = 2 * qt + 2;

    // Q fragments (single fp16) straight from global (a-frag layout)
    uint32_t qf[2][2][4];
    {
        int r = l >> 2, c2 = (l & 3) * 2;
        #pragma unroll
        for (int s = 0; s < 2; s++)
            #pragma unroll
            for (int ks2 = 0; ks2 < 2; ks2++) {
                size_t p = (size_t)(bT + qr0 + w * 32 + s * 16 + r) * CE
                           + hoff + ks2 * 16 + c2;
                qf[s][ks2][0] = *(const uint32_t*)(g_q + p);
                qf[s][ks2][1] = *(const uint32_t*)(g_q + p + 8 * CE);
                qf[s][ks2][2] = *(const uint32_t*)(g_q + p + 8);
                qf[s][ks2][3] = *(const uint32_t*)(g_q + p + 8 * CE + 8);
            }
    }

    auto prefetch = [&](int st, int kt) {
        int kn0 = kt * 64;
        #pragma unroll
        for (int it = 0; it < 4; it++) {
            const int arr = it >> 1;             // 0=k 1=v
            int sub = tid + (it & 1) * 128;
            int row = sub >> 2, j = sub & 3;
            const __half* gp = (arr == 0) ? g_k : g_v;
            const __half* src = gp + (size_t)(bT + kn0 + row) * CE + hoff + j * 8;
            cp16(smem_u32(&sm[st][arr][row * 40 + j * 8]), src);
        }
        asm volatile("cp.async.commit_group;" ::: "memory");
    };

    auto softmax_update = [&](float (&s)[8][4], float* m2, float* li, float (&o)[4][4]) {
        float mx0 = -1e30f, mx1 = -1e30f;
        #pragma unroll
        for (int nt = 0; nt < 8; nt++) {
            mx0 = fmaxf(mx0, fmaxf(s[nt][0], s[nt][1]));
            mx1 = fmaxf(mx1, fmaxf(s[nt][2], s[nt][3]));
        }
        mx0 = fmaxf(mx0, __shfl_xor_sync(0xffffffffu, mx0, 1));
        mx0 = fmaxf(mx0, __shfl_xor_sync(0xffffffffu, mx0, 2));
        mx1 = fmaxf(mx1, __shfl_xor_sync(0xffffffffu, mx1, 1));
        mx1 = fmaxf(mx1, __shfl_xor_sync(0xffffffffu, mx1, 2));
        float mn0 = fmaxf(m2[0], mx0), mn1 = fmaxf(m2[1], mx1);
        float al0 = ex2f(m2[0] - mn0), al1 = ex2f(m2[1] - mn1);
        m2[0] = mn0; m2[1] = mn1;
        float rs0 = 0.f, rs1 = 0.f;
        #pragma unroll
        for (int nt = 0; nt < 8; nt++) {
            s[nt][0] = ex2f(s[nt][0] - mn0);
            s[nt][1] = ex2f(s[nt][1] - mn0);
            s[nt][2] = ex2f(s[nt][2] - mn1);
            s[nt][3] = ex2f(s[nt][3] - mn1);
            rs0 += s[nt][0] + s[nt][1];
            rs1 += s[nt][2] + s[nt][3];
        }
        rs0 += __shfl_xor_sync(0xffffffffu, rs0, 1);
        rs0 += __shfl_xor_sync(0xffffffffu, rs0, 2);
        rs1 += __shfl_xor_sync(0xffffffffu, rs1, 1);
        rs1 += __shfl_xor_sync(0xffffffffu, rs1, 2);
        li[0] = li[0] * al0 + rs0;
        li[1] = li[1] * al1 + rs1;
        #pragma unroll
        for (int nt = 0; nt < 4; nt++) {
            o[nt][0] *= al0; o[nt][1] *= al0;
            o[nt][2] *= al1; o[nt][3] *= al1;
        }
    };

    float m2[4] = {-1e30f, -1e30f, -1e30f, -1e30f};
    float li[4] = {0.f, 0.f, 0.f, 0.f};
    float o0[4][4], o1[4][4];
    #pragma unroll
    for (int i = 0; i < 4; i++)
        #pragma unroll
        for (int j = 0; j < 4; j++) { o0[i][j] = 0.f; o1[i][j] = 0.f; }

    prefetch(0, 0);
    prefetch(1, 1);   // nkv >= 2 always

    for (int kt = 0; kt < nkv; kt++) {
        const int kn0 = kt * 64;
        const int st = kt & 3;
        if (kt + 1 < nkv) {
            asm volatile("cp.async.wait_group 1;" ::: "memory");
        } else {
            asm volatile("cp.async.wait_group 0;" ::: "memory");
        }
        __syncthreads();
        // prefetch 2 ahead: writes the stage last read 4 iters ago (barrier-safe)
        if (kt + 2 < nkv) prefetch((kt + 2) & 3, kt + 2);

        if (kn0 <= qr0 + w * 32 + 31) {  // warp has unmasked work
            const __half* KS = sm[st][0];
            const __half* VS = sm[st][1];

            float s0[8][4], s1[8][4];
            #pragma unroll
            for (int i = 0; i < 8; i++)
                #pragma unroll
                for (int j = 0; j < 4; j++) { s0[i][j] = 0.f; s1[i][j] = 0.f; }

            // ---- S = Q @ K^T (K frags shared by both strips) ----
            #pragma unroll
            for (int ks2 = 0; ks2 < 2; ks2++) {
                #pragma unroll
                for (int np = 0; np < 4; np++) {
                    int off = (np * 16 + ((l >> 4) & 1) * 8 + (l & 7)) * 40
                              + ks2 * 16 + ((l >> 3) & 1) * 8;
                    uint32_t k0, k1, k2, k3;
                    ldmx4(k0, k1, k2, k3, smem_u32(KS + off));
                    mma16816h(s0[2 * np],     qf[0][ks2], k0, k1);
                    mma16816h(s0[2 * np + 1], qf[0][ks2], k2, k3);
                    mma16816h(s1[2 * np],     qf[1][ks2], k0, k1);
                    mma16816h(s1[2 * np + 1], qf[1][ks2], k2, k3);
                }
            }

            // ---- causal mask ----
            if (kn0 + 63 > qr0 + w * 32) {
                int r0 = qr0 + w * 32 + (l >> 2);
                #pragma unroll
                for (int nt = 0; nt < 8; nt++) {
                    int c = kn0 + nt * 8 + (l & 3) * 2;
                    if (c > r0)          s0[nt][0] = -1e30f;
                    if (c + 1 > r0)      s0[nt][1] = -1e30f;
                    if (c > r0 + 8)      s0[nt][2] = -1e30f;
                    if (c + 1 > r0 + 8)  s0[nt][3] = -1e30f;
                    if (c > r0 + 16)     s1[nt][0] = -1e30f;
                    if (c + 1 > r0 + 16) s1[nt][1] = -1e30f;
                    if (c > r0 + 24)     s1[nt][2] = -1e30f;
                    if (c + 1 > r0 + 24) s1[nt][3] = -1e30f;
                }
            }

            softmax_update(s0, &m2[0], &li[0], o0);
            softmax_update(s1, &m2[2], &li[2], o1);

            // ---- O += fp16(P) @ V (V frags shared by both strips) ----
            #pragma unroll
            for (int kk = 0; kk < 4; kk++) {
                uint32_t a0[4], a1[4];
                a0[0] = packh(s0[2 * kk][0],     s0[2 * kk][1]);
                a0[1] = packh(s0[2 * kk][2],     s0[2 * kk][3]);
                a0[2] = packh(s0[2 * kk + 1][0], s0[2 * kk + 1][1]);
                a0[3] = packh(s0[2 * kk + 1][2], s0[2 * kk + 1][3]);
                a1[0] = packh(s1[2 * kk][0],     s1[2 * kk][1]);
                a1[1] = packh(s1[2 * kk][2],     s1[2 * kk][3]);
                a1[2] = packh(s1[2 * kk + 1][0], s1[2 * kk + 1][1]);
                a1[3] = packh(s1[2 * kk + 1][2], s1[2 * kk + 1][3]);
                #pragma unroll
                for (int np = 0; np < 2; np++) {
                    int off = (kk * 16 + ((l >> 3) & 1) * 8 + (l & 7)) * 40
                              + np * 16 + ((l >> 4) & 1) * 8;
                    uint32_t v0, v1, v2, v3;
                    ldmx4t(v0, v1, v2, v3, smem_u32(VS + off));
                    mma16816h(o0[2 * np],     a0, v0, v1);
                    mma16816h(o0[2 * np + 1], a0, v2, v3);
                    mma16816h(o1[2 * np],     a1, v0, v1);
                    mma16816h(o1[2 * np + 1], a1, v2, v3);
                }
            }
        }
    }

    // ---- epilogue: normalize, write fp32 y ----
    #pragma unroll
    for (int s = 0; s < 2; s++) {
        float (&o)[4][4] = s ? o1 : o0;
        #pragma unroll
        for (int g = 0; g < 2; g++) {
            float inv = 1.f / li[s * 2 + g];
            int row = qr0 + w * 32 + s * 16 + g * 8 + (l >> 2);
            size_t yb = (size_t)(bT + row) * CE + hoff;
            #pragma unroll
            for (int nt = 0; nt < 4; nt++) {
                int d = nt * 8 + (l & 3) * 2;
                *(float2*)(g_y + yb + d) =
                    make_float2(o[nt][g * 2] * inv, o[nt][g * 2 + 1] * inv);
            }
        }
    }
}

// ---------------------------------------------------------------------------
extern "C" void kernel_launch(void* const* d_in, const int* in_sizes, int n_in,
                              void* d_out, int out_size)
{
    const float* x      = (const float*)d_in[0];
    const float* w_qkv  = (const float*)d_in[1];
    const float* b_qkv  = (const float*)d_in[2];
    const float* w_proj = (const float*)d_in[3];
    const float* b_proj = (const float*)d_in[4];
    float* out = (float*)d_out;

    // 1) qkv projection -> g_q/g_k/g_v fp16 (q pre-scaled), A staged once
    gemm_mma<0><<<NTOK / 64, 128>>>(x, w_qkv, b_qkv, nullptr, QKVS);

    // 2) attention (single fp16) -> g_y (fp32)
    attn_mma<<<dim3(T_ / 128, NH, B_), 128>>>();

    // 3) out = g_y @ w_proj + b_proj
    gemm_mma<1><<<NTOK / 64, 128>>>(nullptr, w_proj, b_proj, out, CE);
}